// round 9
// baseline (speedup 1.0000x reference)
#include <cuda_runtime.h>
#include <cuda_bf16.h>
#include <mma.h>
#include <cstddef>
#include <cstdint>

using namespace nvcuda;

#define B_ 4
#define T_ 1024
#define D_ 512
#define H_ 16
#define DH_ 32
#define BT_ (B_ * T_)

// ---- scratch (static device globals; no runtime allocation) ----
__device__ float g_qh[BT_ * D_];
__device__ float g_kh[BT_ * D_];
__device__ float g_vh[BT_ * D_];
__device__ float g_ph[BT_ * D_];
__device__ float g_ctx[BT_ * D_];
__device__ float g_P[(size_t)B_ * H_ * T_ * T_];  // 256 MB, unshifted pos scores

__device__ __nv_bfloat16 g_inh[4 * BT_ * D_];   // hi(q,k,v,pos)
__device__ __nv_bfloat16 g_inl[4 * BT_ * D_];   // lo
__device__ __nv_bfloat16 g_wth[3 * D_ * D_];    // hi(Wq^T, Wp^T, Wf^T)  [n][k]
__device__ __nv_bfloat16 g_wtl[3 * D_ * D_];
__device__ __nv_bfloat16 g_ctxh[BT_ * D_];
__device__ __nv_bfloat16 g_ctxl[BT_ * D_];
// post-projection splits
__device__ __nv_bfloat16 g_cqh[BT_ * D_];       // hi(qh + u_bias)
__device__ __nv_bfloat16 g_cql[BT_ * D_];
__device__ __nv_bfloat16 g_khh[BT_ * D_];       // hi(kh)
__device__ __nv_bfloat16 g_khl[BT_ * D_];
__device__ __nv_bfloat16 g_vhh[BT_ * D_];       // hi(vh)
__device__ __nv_bfloat16 g_vhl[BT_ * D_];
__device__ __nv_bfloat16 g_aqh[BT_ * D_];       // hi(qh + v_bias)
__device__ __nv_bfloat16 g_aql[BT_ * D_];
__device__ __nv_bfloat16 g_phh[BT_ * D_];       // hi(ph)
__device__ __nv_bfloat16 g_phl[BT_ * D_];

// =====================================================================
// fp32 -> bf16 hi/lo split converters
// =====================================================================
__device__ __forceinline__ void split_bf16(float x, __nv_bfloat16& h, __nv_bfloat16& l) {
  h = __float2bfloat16(x);
  l = __float2bfloat16(x - __bfloat162float(h));
}

__device__ __forceinline__ void split_store4(float4 x, __nv_bfloat16* Hh,
                                             __nv_bfloat16* Ll, size_t i) {
  __nv_bfloat162 h0, h1, l0, l1;
  split_bf16(x.x, h0.x, l0.x); split_bf16(x.y, h0.y, l0.y);
  split_bf16(x.z, h1.x, l1.x); split_bf16(x.w, h1.y, l1.y);
  *reinterpret_cast<__nv_bfloat162*>(&Hh[i]) = h0;
  *reinterpret_cast<__nv_bfloat162*>(&Hh[i + 2]) = h1;
  *reinterpret_cast<__nv_bfloat162*>(&Ll[i]) = l0;
  *reinterpret_cast<__nv_bfloat162*>(&Ll[i + 2]) = l1;
}

__global__ __launch_bounds__(256) void convert_inputs_kernel(
    const float* __restrict__ q, const float* __restrict__ k,
    const float* __restrict__ v, const float* __restrict__ pos) {
  const int z = blockIdx.y;
  const float* src = (z == 0) ? q : (z == 1) ? k : (z == 2) ? v : pos;
  const size_t i = ((size_t)blockIdx.x * 256 + threadIdx.x) * 4;
  split_store4(*reinterpret_cast<const float4*>(&src[i]),
               g_inh + (size_t)z * BT_ * D_, g_inl + (size_t)z * BT_ * D_, i);
}

__global__ __launch_bounds__(256) void convert_ctx_kernel() {
  const size_t i = ((size_t)blockIdx.x * 256 + threadIdx.x) * 4;
  split_store4(*reinterpret_cast<const float4*>(&g_ctx[i]), g_ctxh, g_ctxl, i);
}

// post-projection splits: z=0 cq(qh+ub), 1 kh, 2 vh, 3 aq(qh+vb), 4 ph
__global__ __launch_bounds__(256) void convert_post_kernel(
    const float* __restrict__ ub, const float* __restrict__ vb) {
  const int z = blockIdx.y;
  const size_t i = ((size_t)blockIdx.x * 256 + threadIdx.x) * 4;
  const int d = (int)(i & (D_ - 1));
  const float* src = (z == 1) ? g_kh : (z == 2) ? g_vh : (z == 4) ? g_ph : g_qh;
  float4 x = *reinterpret_cast<const float4*>(&src[i]);
  if (z == 0 || z == 3) {
    const float* bias = (z == 0) ? ub : vb;
    float4 bb = *reinterpret_cast<const float4*>(&bias[d]);
    x.x += bb.x; x.y += bb.y; x.z += bb.z; x.w += bb.w;
  }
  __nv_bfloat16* Hh = (z == 0) ? g_cqh : (z == 1) ? g_khh : (z == 2) ? g_vhh
                    : (z == 3) ? g_aqh : g_phh;
  __nv_bfloat16* Ll = (z == 0) ? g_cql : (z == 1) ? g_khl : (z == 2) ? g_vhl
                    : (z == 3) ? g_aql : g_phl;
  split_store4(x, Hh, Ll, i);
}

// W [k][n] -> Wt [n][k] hi/lo bf16 (32x32 smem tile transpose)
__global__ __launch_bounds__(256) void convert_w_kernel(
    const float* __restrict__ Wq, const float* __restrict__ Wp,
    const float* __restrict__ Wf) {
  const int z = blockIdx.z;
  const float* W = (z == 0) ? Wq : (z == 1) ? Wp : Wf;
  __nv_bfloat16* Hh = g_wth + (size_t)z * D_ * D_;
  __nv_bfloat16* Ll = g_wtl + (size_t)z * D_ * D_;
  __shared__ float tile[32][33];
  const int tx = threadIdx.x & 31, ty = threadIdx.x >> 5;
  const int k0 = blockIdx.y * 32, n0 = blockIdx.x * 32;
#pragma unroll
  for (int r = 0; r < 4; r++)
    tile[ty + 8 * r][tx] = W[(size_t)(k0 + ty + 8 * r) * D_ + n0 + tx];
  __syncthreads();
#pragma unroll
  for (int r = 0; r < 4; r++) {
    const int n = n0 + ty + 8 * r;
    float x = tile[tx][ty + 8 * r];
    __nv_bfloat16 h, l; split_bf16(x, h, l);
    Hh[(size_t)n * D_ + k0 + tx] = h;
    Ll[(size_t)n * D_ + k0 + tx] = l;
  }
}

// =====================================================================
// wmma split-bf16 GEMM (validated round 6)
// =====================================================================
#define ALD 40

__device__ __forceinline__ void wmma_gemm_body(
    const __nv_bfloat16* __restrict__ Ah, const __nv_bfloat16* __restrict__ Al,
    const __nv_bfloat16* __restrict__ Bh, const __nv_bfloat16* __restrict__ Bl,
    const float* __restrict__ bias, float* __restrict__ C, int m0, int n0) {
  __shared__ __align__(16) char smraw[32768];
  __nv_bfloat16* aH = reinterpret_cast<__nv_bfloat16*>(smraw);
  __nv_bfloat16* aL = aH + 128 * ALD;
  __nv_bfloat16* bH = aL + 128 * ALD;
  __nv_bfloat16* bL = bH + 64 * ALD;

  const int tid = threadIdx.x;
  const int wid = tid >> 5;
  const int wm = wid >> 1, wn = wid & 1;

  wmma::fragment<wmma::accumulator, 16, 16, 16, float> acc[2][2];
#pragma unroll
  for (int i = 0; i < 2; i++)
#pragma unroll
    for (int j = 0; j < 2; j++) wmma::fill_fragment(acc[i][j], 0.f);

  for (int k0 = 0; k0 < 512; k0 += 32) {
#pragma unroll
    for (int r2 = 0; r2 < 2; r2++) {
      const int idx = tid + r2 * 256;
      const int r = idx >> 2, c8 = (idx & 3) * 8;
      const size_t g = (size_t)(m0 + r) * D_ + k0 + c8;
      *reinterpret_cast<uint4*>(&aH[r * ALD + c8]) = *reinterpret_cast<const uint4*>(&Ah[g]);
      *reinterpret_cast<uint4*>(&aL[r * ALD + c8]) = *reinterpret_cast<const uint4*>(&Al[g]);
    }
    {
      const int r = tid >> 2, c8 = (tid & 3) * 8;
      const size_t g = (size_t)(n0 + r) * D_ + k0 + c8;
      *reinterpret_cast<uint4*>(&bH[r * ALD + c8]) = *reinterpret_cast<const uint4*>(&Bh[g]);
      *reinterpret_cast<uint4*>(&bL[r * ALD + c8]) = *reinterpret_cast<const uint4*>(&Bl[g]);
    }
    __syncthreads();
#pragma unroll
    for (int kk = 0; kk < 32; kk += 16) {
      wmma::fragment<wmma::matrix_a, 16, 16, 16, __nv_bfloat16, wmma::row_major> fah[2], fal[2];
      wmma::fragment<wmma::matrix_b, 16, 16, 16, __nv_bfloat16, wmma::col_major> fbh[2], fbl[2];
#pragma unroll
      for (int i = 0; i < 2; i++) {
        wmma::load_matrix_sync(fah[i], &aH[(wm * 32 + i * 16) * ALD + kk], ALD);
        wmma::load_matrix_sync(fal[i], &aL[(wm * 32 + i * 16) * ALD + kk], ALD);
        wmma::load_matrix_sync(fbh[i], &bH[(wn * 32 + i * 16) * ALD + kk], ALD);
        wmma::load_matrix_sync(fbl[i], &bL[(wn * 32 + i * 16) * ALD + kk], ALD);
      }
#pragma unroll
      for (int i = 0; i < 2; i++)
#pragma unroll
        for (int j = 0; j < 2; j++) {
          wmma::mma_sync(acc[i][j], fah[i], fbh[j], acc[i][j]);
          wmma::mma_sync(acc[i][j], fah[i], fbl[j], acc[i][j]);
          wmma::mma_sync(acc[i][j], fal[i], fbh[j], acc[i][j]);
        }
    }
    __syncthreads();
  }

  float* Cs = reinterpret_cast<float*>(smraw);
#pragma unroll
  for (int i = 0; i < 2; i++)
#pragma unroll
    for (int j = 0; j < 2; j++)
      wmma::store_matrix_sync(&Cs[(wm * 32 + i * 16) * 64 + wn * 32 + j * 16],
                              acc[i][j], 64, wmma::mem_row_major);
  __syncthreads();
#pragma unroll
  for (int r2 = 0; r2 < 8; r2++) {
    const int idx = tid + r2 * 256;
    const int row = idx >> 4, c4 = (idx & 15) * 4;
    float4 o = *reinterpret_cast<const float4*>(&Cs[row * 64 + c4]);
    if (bias) {
      float4 bb = *reinterpret_cast<const float4*>(&bias[n0 + c4]);
      o.x += bb.x; o.y += bb.y; o.z += bb.z; o.w += bb.w;
    }
    *reinterpret_cast<float4*>(&C[(size_t)(m0 + row) * D_ + n0 + c4]) = o;
  }
}

__global__ __launch_bounds__(256) void wmma_proj_kernel(const float* __restrict__ bq) {
  const int z = blockIdx.z;
  const __nv_bfloat16* Ah = g_inh + (size_t)z * BT_ * D_;
  const __nv_bfloat16* Al = g_inl + (size_t)z * BT_ * D_;
  const int ws = (z < 3) ? 0 : 1;
  float* C = (z == 0) ? g_qh : (z == 1) ? g_kh : (z == 2) ? g_vh : g_ph;
  wmma_gemm_body(Ah, Al, g_wth + (size_t)ws * D_ * D_, g_wtl + (size_t)ws * D_ * D_,
                 (z < 3) ? bq : nullptr, C, blockIdx.y * 128, blockIdx.x * 64);
}

__global__ __launch_bounds__(256) void wmma_final_kernel(const float* __restrict__ bf,
                                                         float* __restrict__ out) {
  wmma_gemm_body(g_ctxh, g_ctxl, g_wth + (size_t)2 * D_ * D_, g_wtl + (size_t)2 * D_ * D_,
                 bf, out, blockIdx.y * 128, blockIdx.x * 64);
}

// =====================================================================
// wmma pscore (validated round 6)
// =====================================================================
__global__ __launch_bounds__(256) void wmma_pscore_kernel() {
  __shared__ __align__(16) __nv_bfloat16 aH[128 * ALD];
  __shared__ __align__(16) __nv_bfloat16 aL[128 * ALD];
  __shared__ __align__(16) __nv_bfloat16 bH[128 * ALD];
  __shared__ __align__(16) __nv_bfloat16 bL[128 * ALD];

  const int tid = threadIdx.x;
  const int wid = tid >> 5;
  const int wm = wid >> 1, wn = wid & 1;
  const int bz = blockIdx.z, b = bz >> 4, h = bz & 15;
  const int t0 = blockIdx.y * 128, j0 = blockIdx.x * 128;

#pragma unroll
  for (int r2 = 0; r2 < 2; r2++) {
    const int idx = tid + r2 * 256;
    const int r = idx >> 2, c8 = (idx & 3) * 8;
    const size_t ga = (size_t)(b * T_ + t0 + r) * D_ + h * DH_ + c8;
    const size_t gb = (size_t)(b * T_ + j0 + r) * D_ + h * DH_ + c8;
    *reinterpret_cast<uint4*>(&aH[r * ALD + c8]) = *reinterpret_cast<const uint4*>(&g_aqh[ga]);
    *reinterpret_cast<uint4*>(&aL[r * ALD + c8]) = *reinterpret_cast<const uint4*>(&g_aql[ga]);
    *reinterpret_cast<uint4*>(&bH[r * ALD + c8]) = *reinterpret_cast<const uint4*>(&g_phh[gb]);
    *reinterpret_cast<uint4*>(&bL[r * ALD + c8]) = *reinterpret_cast<const uint4*>(&g_phl[gb]);
  }
  __syncthreads();

  wmma::fragment<wmma::accumulator, 16, 16, 16, float> acc[2][4];
#pragma unroll
  for (int i = 0; i < 2; i++)
#pragma unroll
    for (int j = 0; j < 4; j++) wmma::fill_fragment(acc[i][j], 0.f);

#pragma unroll
  for (int kk = 0; kk < 32; kk += 16) {
    wmma::fragment<wmma::matrix_a, 16, 16, 16, __nv_bfloat16, wmma::row_major> fah[2], fal[2];
    wmma::fragment<wmma::matrix_b, 16, 16, 16, __nv_bfloat16, wmma::col_major> fbh[4], fbl[4];
#pragma unroll
    for (int i = 0; i < 2; i++) {
      wmma::load_matrix_sync(fah[i], &aH[(wm * 32 + i * 16) * ALD + kk], ALD);
      wmma::load_matrix_sync(fal[i], &aL[(wm * 32 + i * 16) * ALD + kk], ALD);
    }
#pragma unroll
    for (int j = 0; j < 4; j++) {
      wmma::load_matrix_sync(fbh[j], &bH[(wn * 64 + j * 16) * ALD + kk], ALD);
      wmma::load_matrix_sync(fbl[j], &bL[(wn * 64 + j * 16) * ALD + kk], ALD);
    }
#pragma unroll
    for (int i = 0; i < 2; i++)
#pragma unroll
      for (int j = 0; j < 4; j++) {
        wmma::mma_sync(acc[i][j], fah[i], fbh[j], acc[i][j]);
        wmma::mma_sync(acc[i][j], fah[i], fbl[j], acc[i][j]);
        wmma::mma_sync(acc[i][j], fal[i], fbh[j], acc[i][j]);
      }
  }

#pragma unroll
  for (int i = 0; i < 2; i++)
#pragma unroll
    for (int j = 0; j < 4; j++) {
      float* dst = &g_P[((size_t)bz * T_ + t0 + wm * 32 + i * 16) * T_ + j0 + wn * 64 + j * 16];
      wmma::store_matrix_sync(dst, acc[i][j], T_, wmma::mem_row_major);
    }
}

// =====================================================================
// wmma flash v2: content score (wmma) + shift(P) + softmax (fixed shift)
// + AV (wmma, persistent fragments).
// Fixes vs v1: (a) epilogue gather is COALESCED (lane sweeps s);
// (b) K/V for chunk c+1 prefetched into registers during epilogue,
//     stored after the AV sync (latency hidden behind AV HMMAs);
// (c) row-sum kept in 8 per-thread registers, single end reduction.
// =====================================================================
#define SLD 68   // fp32 score tile ld
#define PLD 72   // bf16 prob tile ld
#define CLD 36   // fp32 out tile ld
#define OFF_QH 0
#define OFF_QL (OFF_QH + 64 * ALD * 2)
#define OFF_KH (OFF_QL + 64 * ALD * 2)
#define OFF_KL (OFF_KH + 64 * ALD * 2)
#define OFF_VH (OFF_KL + 64 * ALD * 2)
#define OFF_VL (OFF_VH + 64 * ALD * 2)
#define OFF_SS (OFF_VL + 64 * ALD * 2)
#define OFF_PH (OFF_SS + 64 * SLD * 4)
#define OFF_PL (OFF_PH + 64 * PLD * 2)
#define OFF_LR (OFF_PL + 64 * PLD * 2)
#define FLASH_SMEM (OFF_LR + 64 * 4)

__global__ __launch_bounds__(256) void flash_wmma_kernel() {
  extern __shared__ __align__(16) char sm[];
  __nv_bfloat16* Qh = reinterpret_cast<__nv_bfloat16*>(sm + OFF_QH);
  __nv_bfloat16* Ql = reinterpret_cast<__nv_bfloat16*>(sm + OFF_QL);
  __nv_bfloat16* Kh = reinterpret_cast<__nv_bfloat16*>(sm + OFF_KH);
  __nv_bfloat16* Kl = reinterpret_cast<__nv_bfloat16*>(sm + OFF_KL);
  __nv_bfloat16* Vh = reinterpret_cast<__nv_bfloat16*>(sm + OFF_VH);
  __nv_bfloat16* Vl = reinterpret_cast<__nv_bfloat16*>(sm + OFF_VL);
  float* Ss = reinterpret_cast<float*>(sm + OFF_SS);
  __nv_bfloat16* Ph = reinterpret_cast<__nv_bfloat16*>(sm + OFF_PH);
  __nv_bfloat16* Pl = reinterpret_cast<__nv_bfloat16*>(sm + OFF_PL);
  float* lrow = reinterpret_cast<float*>(sm + OFF_LR);

  const int tid = threadIdx.x;
  const int wid = tid >> 5, lane = tid & 31;
  const int wm = wid >> 1, wn = wid & 1;   // 4 x 2 warp grid
  const int bz = blockIdx.y, b = bz >> 4, h = bz & 15;
  const int t0 = blockIdx.x * 64;
  const float isd = 0.04419417382415922f;  // 1/sqrt(512)

  // load Q tile (64 x 32) hi/lo, resident
  const int pr = tid >> 2, pc8 = (tid & 3) * 8;
  {
    const size_t g = (size_t)(b * T_ + t0 + pr) * D_ + h * DH_ + pc8;
    *reinterpret_cast<uint4*>(&Qh[pr * ALD + pc8]) = *reinterpret_cast<const uint4*>(&g_cqh[g]);
    *reinterpret_cast<uint4*>(&Ql[pr * ALD + pc8]) = *reinterpret_cast<const uint4*>(&g_cql[g]);
  }

  float lsum8[8];
#pragma unroll
  for (int i = 0; i < 8; i++) lsum8[i] = 0.f;

  wmma::fragment<wmma::accumulator, 16, 16, 16, float> accO;
  wmma::fill_fragment(accO, 0.f);

  // prefetch chunk 0 K/V into registers
  uint4 rkh, rkl, rvh, rvl;
  {
    const size_t g = (size_t)(b * T_ + 0 + pr) * D_ + h * DH_ + pc8;
    rkh = *reinterpret_cast<const uint4*>(&g_khh[g]);
    rkl = *reinterpret_cast<const uint4*>(&g_khl[g]);
    rvh = *reinterpret_cast<const uint4*>(&g_vhh[g]);
    rvl = *reinterpret_cast<const uint4*>(&g_vhl[g]);
  }

  for (int c = 0; c < 16; c++) {
    const int s0 = c * 64;
    // commit prefetched K/V to smem
    *reinterpret_cast<uint4*>(&Kh[pr * ALD + pc8]) = rkh;
    *reinterpret_cast<uint4*>(&Kl[pr * ALD + pc8]) = rkl;
    *reinterpret_cast<uint4*>(&Vh[pr * ALD + pc8]) = rvh;
    *reinterpret_cast<uint4*>(&Vl[pr * ALD + pc8]) = rvl;
    __syncthreads();

    // ---- QK^T: warp computes 16 x 32 stripe of 64 x 64 S ----
    {
      wmma::fragment<wmma::accumulator, 16, 16, 16, float> accS[2];
      wmma::fill_fragment(accS[0], 0.f);
      wmma::fill_fragment(accS[1], 0.f);
#pragma unroll
      for (int kk = 0; kk < 32; kk += 16) {
        wmma::fragment<wmma::matrix_a, 16, 16, 16, __nv_bfloat16, wmma::row_major> fah, fal;
        wmma::load_matrix_sync(fah, &Qh[(wm * 16) * ALD + kk], ALD);
        wmma::load_matrix_sync(fal, &Ql[(wm * 16) * ALD + kk], ALD);
#pragma unroll
        for (int j = 0; j < 2; j++) {
          wmma::fragment<wmma::matrix_b, 16, 16, 16, __nv_bfloat16, wmma::col_major> fbh, fbl;
          wmma::load_matrix_sync(fbh, &Kh[(wn * 32 + j * 16) * ALD + kk], ALD);
          wmma::load_matrix_sync(fbl, &Kl[(wn * 32 + j * 16) * ALD + kk], ALD);
          wmma::mma_sync(accS[j], fah, fbh, accS[j]);
          wmma::mma_sync(accS[j], fah, fbl, accS[j]);
          wmma::mma_sync(accS[j], fal, fbh, accS[j]);
        }
      }
      wmma::store_matrix_sync(&Ss[(wm * 16) * SLD + wn * 32], accS[0], SLD,
                              wmma::mem_row_major);
      wmma::store_matrix_sync(&Ss[(wm * 16) * SLD + wn * 32 + 16], accS[1], SLD,
                              wmma::mem_row_major);
    }
    __syncthreads();

    // ---- epilogue: +shiftP (COALESCED: lane sweeps s), exp, split ----
    {
      const int r0 = wid * 8;
#pragma unroll
      for (int rr = 0; rr < 8; rr++) {
        const int r = r0 + rr;
        const int t = t0 + r;
        const size_t rowb = ((size_t)bz * T_ + t) * T_;
        float acc = 0.f;
#pragma unroll
        for (int half = 0; half < 2; half++) {
          const int sc = half * 32 + lane;
          const int s = s0 + sc;
          float pv;
          if (s <= t)          pv = g_P[rowb + (s - t + (T_ - 1))];
          else if (s == t + 1) pv = 0.f;
          else                 pv = g_P[rowb + T_ + (s - t - 2)];
          float e = __expf((Ss[r * SLD + sc] + pv) * isd);
          acc += e;
          __nv_bfloat16 eh, el; split_bf16(e, eh, el);
          Ph[r * PLD + sc] = eh;
          Pl[r * PLD + sc] = el;
        }
        lsum8[rr] += acc;
      }
    }
    // prefetch next chunk's K/V (latency hidden behind AV below)
    if (c + 1 < 16) {
      const size_t g = (size_t)(b * T_ + (s0 + 64) + pr) * D_ + h * DH_ + pc8;
      rkh = *reinterpret_cast<const uint4*>(&g_khh[g]);
      rkl = *reinterpret_cast<const uint4*>(&g_khl[g]);
      rvh = *reinterpret_cast<const uint4*>(&g_vhh[g]);
      rvl = *reinterpret_cast<const uint4*>(&g_vhl[g]);
    }
    __syncthreads();

    // ---- AV: warp frag (wm*16 rows) x (wn*16 cols), K = 64 ----
#pragma unroll
    for (int kk = 0; kk < 64; kk += 16) {
      wmma::fragment<wmma::matrix_a, 16, 16, 16, __nv_bfloat16, wmma::row_major> pah, pal;
      wmma::fragment<wmma::matrix_b, 16, 16, 16, __nv_bfloat16, wmma::row_major> fvh, fvl;
      wmma::load_matrix_sync(pah, &Ph[(wm * 16) * PLD + kk], PLD);
      wmma::load_matrix_sync(pal, &Pl[(wm * 16) * PLD + kk], PLD);
      wmma::load_matrix_sync(fvh, &Vh[kk * ALD + wn * 16], ALD);
      wmma::load_matrix_sync(fvl, &Vl[kk * ALD + wn * 16], ALD);
      wmma::mma_sync(accO, pah, fvh, accO);
      wmma::mma_sync(accO, pah, fvl, accO);
      wmma::mma_sync(accO, pal, fvh, accO);
    }
    __syncthreads();
  }

  // ---- finalize: reduce row sums across lanes, normalize, store ----
#pragma unroll
  for (int rr = 0; rr < 8; rr++) {
    float l = lsum8[rr];
#pragma unroll
    for (int o = 16; o > 0; o >>= 1) l += __shfl_xor_sync(0xffffffffu, l, o);
    if (lane == 0) lrow[wid * 8 + rr] = 1.0f / l;
  }
  float* Cs = Ss;
  wmma::store_matrix_sync(&Cs[(wm * 16) * CLD + wn * 16], accO, CLD,
                          wmma::mem_row_major);
  __syncthreads();
  {
    const int row = tid >> 2, c8 = (tid & 3) * 8;
    const float inv = lrow[row];
    float4 a = *reinterpret_cast<const float4*>(&Cs[row * CLD + c8]);
    float4 bb = *reinterpret_cast<const float4*>(&Cs[row * CLD + c8 + 4]);
    a.x *= inv; a.y *= inv; a.z *= inv; a.w *= inv;
    bb.x *= inv; bb.y *= inv; bb.z *= inv; bb.w *= inv;
    const size_t base = (size_t)(b * T_ + t0 + row) * D_ + h * DH_ + c8;
    *reinterpret_cast<float4*>(&g_ctx[base]) = a;
    *reinterpret_cast<float4*>(&g_ctx[base + 4]) = bb;
  }
}

// =====================================================================
extern "C" void kernel_launch(void* const* d_in, const int* in_sizes, int n_in,
                              void* d_out, int out_size) {
  const float* q   = (const float*)d_in[0];
  const float* k   = (const float*)d_in[1];
  const float* v   = (const float*)d_in[2];
  const float* pos = (const float*)d_in[3];
  const float* Wq  = (const float*)d_in[4];
  const float* bq  = (const float*)d_in[5];
  const float* Wp  = (const float*)d_in[6];
  const float* Wf  = (const float*)d_in[7];
  const float* bf  = (const float*)d_in[8];
  const float* ub  = (const float*)d_in[9];
  const float* vb  = (const float*)d_in[10];
  float* out = (float*)d_out;

  static bool attr_done = false;
  if (!attr_done) {
    cudaFuncSetAttribute(flash_wmma_kernel,
                         cudaFuncAttributeMaxDynamicSharedMemorySize, FLASH_SMEM);
    attr_done = true;
  }

  convert_inputs_kernel<<<dim3(BT_ * D_ / 1024, 4), 256>>>(q, k, v, pos);
  convert_w_kernel<<<dim3(16, 16, 3), 256>>>(Wq, Wp, Wf);

  wmma_proj_kernel<<<dim3(8, 32, 4), 256>>>(bq);

  convert_post_kernel<<<dim3(BT_ * D_ / 1024, 5), 256>>>(ub, vb);

  wmma_pscore_kernel<<<dim3(8, 8, 64), 256>>>();

  flash_wmma_kernel<<<dim3(16, 64), 256, FLASH_SMEM>>>();

  convert_ctx_kernel<<<BT_ * D_ / 1024, 256>>>();
  wmma_final_kernel<<<dim3(8, 32), 256>>>(bf, out);
}

// round 12
// speedup vs baseline: 1.2950x; 1.2950x over previous
#include <cuda_runtime.h>
#include <cuda_bf16.h>
#include <cuda_fp16.h>
#include <mma.h>
#include <cstddef>
#include <cstdint>

using namespace nvcuda;

#define B_ 4
#define T_ 1024
#define D_ 512
#define H_ 16
#define DH_ 32
#define BT_ (B_ * T_)

typedef unsigned long long u64;

// ---- f32x2 packed-math helpers (sm_103a) ----
__device__ __forceinline__ u64 pack2(float x, float y) {
  u64 r; asm("mov.b64 %0, {%1, %2};" : "=l"(r) : "f"(x), "f"(y)); return r;
}
__device__ __forceinline__ void fma2(u64& d, u64 a, u64 b) {
  asm("fma.rn.f32x2 %0, %1, %2, %0;" : "+l"(d) : "l"(a), "l"(b));
}
__device__ __forceinline__ void mul2(u64& d, u64 a) {
  asm("mul.rn.f32x2 %0, %0, %1;" : "+l"(d) : "l"(a));
}
__device__ __forceinline__ float2 unpack2(u64 v) {
  float2 f; asm("mov.b64 {%0, %1}, %2;" : "=f"(f.x), "=f"(f.y) : "l"(v)); return f;
}

// ---- scratch (static device globals; no runtime allocation) ----
__device__ float g_qh[BT_ * D_];
__device__ float g_kh[BT_ * D_];
__device__ float g_vh[BT_ * D_];
__device__ __half g_P[(size_t)B_ * H_ * T_ * T_];  // 128 MB, unshifted pos scores

__device__ __nv_bfloat16 g_inh[4 * BT_ * D_];   // hi(q,k,v,pos)
__device__ __nv_bfloat16 g_inl[4 * BT_ * D_];   // lo
__device__ __nv_bfloat16 g_wth[3 * D_ * D_];    // hi(Wq^T, Wp^T, Wf^T)  [n][k]
__device__ __nv_bfloat16 g_wtl[3 * D_ * D_];
__device__ __nv_bfloat16 g_ctxh[BT_ * D_];
__device__ __nv_bfloat16 g_ctxl[BT_ * D_];
__device__ __nv_bfloat16 g_cqh[BT_ * D_];       // hi(qh + u_bias) (unused by flash; kept for parity)
__device__ __nv_bfloat16 g_cql[BT_ * D_];
__device__ __nv_bfloat16 g_aqh[BT_ * D_];       // hi(qh + v_bias)
__device__ __nv_bfloat16 g_aql[BT_ * D_];
__device__ __nv_bfloat16 g_phh[BT_ * D_];       // hi(ph)
__device__ __nv_bfloat16 g_phl[BT_ * D_];

// =====================================================================
// fp32 -> bf16 hi/lo split
// =====================================================================
__device__ __forceinline__ void split_bf16(float x, __nv_bfloat16& h, __nv_bfloat16& l) {
  h = __float2bfloat16(x);
  l = __float2bfloat16(x - __bfloat162float(h));
}

__device__ __forceinline__ void split_store4(float4 x, __nv_bfloat16* Hh,
                                             __nv_bfloat16* Ll, size_t i) {
  __nv_bfloat162 h0, h1, l0, l1;
  split_bf16(x.x, h0.x, l0.x); split_bf16(x.y, h0.y, l0.y);
  split_bf16(x.z, h1.x, l1.x); split_bf16(x.w, h1.y, l1.y);
  *reinterpret_cast<__nv_bfloat162*>(&Hh[i]) = h0;
  *reinterpret_cast<__nv_bfloat162*>(&Hh[i + 2]) = h1;
  *reinterpret_cast<__nv_bfloat162*>(&Ll[i]) = l0;
  *reinterpret_cast<__nv_bfloat162*>(&Ll[i + 2]) = l1;
}

__global__ __launch_bounds__(256) void convert_inputs_kernel(
    const float* __restrict__ q, const float* __restrict__ k,
    const float* __restrict__ v, const float* __restrict__ pos) {
  const int z = blockIdx.y;
  const float* src = (z == 0) ? q : (z == 1) ? k : (z == 2) ? v : pos;
  const size_t i = ((size_t)blockIdx.x * 256 + threadIdx.x) * 4;
  split_store4(*reinterpret_cast<const float4*>(&src[i]),
               g_inh + (size_t)z * BT_ * D_, g_inl + (size_t)z * BT_ * D_, i);
}

// W [k][n] -> Wt [n][k] hi/lo bf16 (32x32 smem tile transpose)
__global__ __launch_bounds__(256) void convert_w_kernel(
    const float* __restrict__ Wq, const float* __restrict__ Wp,
    const float* __restrict__ Wf) {
  const int z = blockIdx.z;
  const float* W = (z == 0) ? Wq : (z == 1) ? Wp : Wf;
  __nv_bfloat16* Hh = g_wth + (size_t)z * D_ * D_;
  __nv_bfloat16* Ll = g_wtl + (size_t)z * D_ * D_;
  __shared__ float tile[32][33];
  const int tx = threadIdx.x & 31, ty = threadIdx.x >> 5;
  const int k0 = blockIdx.y * 32, n0 = blockIdx.x * 32;
#pragma unroll
  for (int r = 0; r < 4; r++)
    tile[ty + 8 * r][tx] = W[(size_t)(k0 + ty + 8 * r) * D_ + n0 + tx];
  __syncthreads();
#pragma unroll
  for (int r = 0; r < 4; r++) {
    const int n = n0 + ty + 8 * r;
    float x = tile[tx][ty + 8 * r];
    __nv_bfloat16 h, l; split_bf16(x, h, l);
    Hh[(size_t)n * D_ + k0 + tx] = h;
    Ll[(size_t)n * D_ + k0 + tx] = l;
  }
}

// =====================================================================
// wmma split-bf16 GEMM (validated round 6) with fused split epilogues.
// mode: 0=q (fp32 qh + cq/aq splits), 1=kh fp32, 2=vh fp32,
//       3=ph splits only, 4=final (fp32 out + bias)
// =====================================================================
#define ALD 40

__device__ __forceinline__ void wmma_gemm_body(
    const __nv_bfloat16* __restrict__ Ah, const __nv_bfloat16* __restrict__ Al,
    const __nv_bfloat16* __restrict__ Bh, const __nv_bfloat16* __restrict__ Bl,
    const float* __restrict__ bias, float* __restrict__ C, int m0, int n0,
    int mode, const float* __restrict__ ub, const float* __restrict__ vb) {
  __shared__ __align__(16) char smraw[32768];
  __nv_bfloat16* aH = reinterpret_cast<__nv_bfloat16*>(smraw);
  __nv_bfloat16* aL = aH + 128 * ALD;
  __nv_bfloat16* bH = aL + 128 * ALD;
  __nv_bfloat16* bL = bH + 64 * ALD;

  const int tid = threadIdx.x;
  const int wid = tid >> 5;
  const int wm = wid >> 1, wn = wid & 1;

  wmma::fragment<wmma::accumulator, 16, 16, 16, float> acc[2][2];
#pragma unroll
  for (int i = 0; i < 2; i++)
#pragma unroll
    for (int j = 0; j < 2; j++) wmma::fill_fragment(acc[i][j], 0.f);

  for (int k0 = 0; k0 < 512; k0 += 32) {
#pragma unroll
    for (int r2 = 0; r2 < 2; r2++) {
      const int idx = tid + r2 * 256;
      const int r = idx >> 2, c8 = (idx & 3) * 8;
      const size_t g = (size_t)(m0 + r) * D_ + k0 + c8;
      *reinterpret_cast<uint4*>(&aH[r * ALD + c8]) = *reinterpret_cast<const uint4*>(&Ah[g]);
      *reinterpret_cast<uint4*>(&aL[r * ALD + c8]) = *reinterpret_cast<const uint4*>(&Al[g]);
    }
    {
      const int r = tid >> 2, c8 = (tid & 3) * 8;
      const size_t g = (size_t)(n0 + r) * D_ + k0 + c8;
      *reinterpret_cast<uint4*>(&bH[r * ALD + c8]) = *reinterpret_cast<const uint4*>(&Bh[g]);
      *reinterpret_cast<uint4*>(&bL[r * ALD + c8]) = *reinterpret_cast<const uint4*>(&Bl[g]);
    }
    __syncthreads();
#pragma unroll
    for (int kk = 0; kk < 32; kk += 16) {
      wmma::fragment<wmma::matrix_a, 16, 16, 16, __nv_bfloat16, wmma::row_major> fah[2], fal[2];
      wmma::fragment<wmma::matrix_b, 16, 16, 16, __nv_bfloat16, wmma::col_major> fbh[2], fbl[2];
#pragma unroll
      for (int i = 0; i < 2; i++) {
        wmma::load_matrix_sync(fah[i], &aH[(wm * 32 + i * 16) * ALD + kk], ALD);
        wmma::load_matrix_sync(fal[i], &aL[(wm * 32 + i * 16) * ALD + kk], ALD);
        wmma::load_matrix_sync(fbh[i], &bH[(wn * 32 + i * 16) * ALD + kk], ALD);
        wmma::load_matrix_sync(fbl[i], &bL[(wn * 32 + i * 16) * ALD + kk], ALD);
      }
#pragma unroll
      for (int i = 0; i < 2; i++)
#pragma unroll
        for (int j = 0; j < 2; j++) {
          wmma::mma_sync(acc[i][j], fah[i], fbh[j], acc[i][j]);
          wmma::mma_sync(acc[i][j], fah[i], fbl[j], acc[i][j]);
          wmma::mma_sync(acc[i][j], fal[i], fbh[j], acc[i][j]);
        }
    }
    __syncthreads();
  }

  float* Cs = reinterpret_cast<float*>(smraw);
#pragma unroll
  for (int i = 0; i < 2; i++)
#pragma unroll
    for (int j = 0; j < 2; j++)
      wmma::store_matrix_sync(&Cs[(wm * 32 + i * 16) * 64 + wn * 32 + j * 16],
                              acc[i][j], 64, wmma::mem_row_major);
  __syncthreads();
#pragma unroll
  for (int r2 = 0; r2 < 8; r2++) {
    const int idx = tid + r2 * 256;
    const int row = idx >> 4, c4 = (idx & 15) * 4;
    float4 o = *reinterpret_cast<const float4*>(&Cs[row * 64 + c4]);
    if (bias) {
      float4 bb = *reinterpret_cast<const float4*>(&bias[n0 + c4]);
      o.x += bb.x; o.y += bb.y; o.z += bb.z; o.w += bb.w;
    }
    const size_t g = (size_t)(m0 + row) * D_ + n0 + c4;
    if (mode == 0) {
      *reinterpret_cast<float4*>(&g_qh[g]) = o;
      float4 ub4 = *reinterpret_cast<const float4*>(&ub[n0 + c4]);
      float4 vb4 = *reinterpret_cast<const float4*>(&vb[n0 + c4]);
      float4 cq = make_float4(o.x + ub4.x, o.y + ub4.y, o.z + ub4.z, o.w + ub4.w);
      float4 aq = make_float4(o.x + vb4.x, o.y + vb4.y, o.z + vb4.z, o.w + vb4.w);
      split_store4(cq, g_cqh, g_cql, g);
      split_store4(aq, g_aqh, g_aql, g);
    } else if (mode == 1) {
      *reinterpret_cast<float4*>(&g_kh[g]) = o;
    } else if (mode == 2) {
      *reinterpret_cast<float4*>(&g_vh[g]) = o;
    } else if (mode == 3) {
      split_store4(o, g_phh, g_phl, g);
    } else {
      *reinterpret_cast<float4*>(&C[g]) = o;
    }
  }
}

__global__ __launch_bounds__(256) void wmma_proj_kernel(
    const float* __restrict__ bq, const float* __restrict__ ub,
    const float* __restrict__ vb) {
  const int z = blockIdx.z;
  const __nv_bfloat16* Ah = g_inh + (size_t)z * BT_ * D_;
  const __nv_bfloat16* Al = g_inl + (size_t)z * BT_ * D_;
  const int ws = (z < 3) ? 0 : 1;
  wmma_gemm_body(Ah, Al, g_wth + (size_t)ws * D_ * D_, g_wtl + (size_t)ws * D_ * D_,
                 (z < 3) ? bq : nullptr, nullptr, blockIdx.y * 128, blockIdx.x * 64,
                 z, ub, vb);
}

__global__ __launch_bounds__(256) void wmma_final_kernel(const float* __restrict__ bf,
                                                         float* __restrict__ out) {
  wmma_gemm_body(g_ctxh, g_ctxl, g_wth + (size_t)2 * D_ * D_, g_wtl + (size_t)2 * D_ * D_,
                 bf, out, blockIdx.y * 128, blockIdx.x * 64, 4, nullptr, nullptr);
}

// =====================================================================
// wmma pscore (validated round 6) -> fp16 output via smem staging
// =====================================================================
__global__ __launch_bounds__(256) void wmma_pscore_kernel() {
  __shared__ __align__(16) char psm[40960];
  __nv_bfloat16* aH = reinterpret_cast<__nv_bfloat16*>(psm);
  __nv_bfloat16* aL = aH + 128 * ALD;
  __nv_bfloat16* bH = aL + 128 * ALD;
  __nv_bfloat16* bL = bH + 128 * ALD;

  const int tid = threadIdx.x;
  const int wid = tid >> 5;
  const int wm = wid >> 1, wn = wid & 1;
  const int bz = blockIdx.z, b = bz >> 4, h = bz & 15;
  const int t0 = blockIdx.y * 128, j0 = blockIdx.x * 128;

#pragma unroll
  for (int r2 = 0; r2 < 2; r2++) {
    const int idx = tid + r2 * 256;
    const int r = idx >> 2, c8 = (idx & 3) * 8;
    const size_t ga = (size_t)(b * T_ + t0 + r) * D_ + h * DH_ + c8;
    const size_t gb = (size_t)(b * T_ + j0 + r) * D_ + h * DH_ + c8;
    *reinterpret_cast<uint4*>(&aH[r * ALD + c8]) = *reinterpret_cast<const uint4*>(&g_aqh[ga]);
    *reinterpret_cast<uint4*>(&aL[r * ALD + c8]) = *reinterpret_cast<const uint4*>(&g_aql[ga]);
    *reinterpret_cast<uint4*>(&bH[r * ALD + c8]) = *reinterpret_cast<const uint4*>(&g_phh[gb]);
    *reinterpret_cast<uint4*>(&bL[r * ALD + c8]) = *reinterpret_cast<const uint4*>(&g_phl[gb]);
  }
  __syncthreads();

  wmma::fragment<wmma::accumulator, 16, 16, 16, float> acc[2][4];
#pragma unroll
  for (int i = 0; i < 2; i++)
#pragma unroll
    for (int j = 0; j < 4; j++) wmma::fill_fragment(acc[i][j], 0.f);

#pragma unroll
  for (int kk = 0; kk < 32; kk += 16) {
    wmma::fragment<wmma::matrix_a, 16, 16, 16, __nv_bfloat16, wmma::row_major> fah[2], fal[2];
    wmma::fragment<wmma::matrix_b, 16, 16, 16, __nv_bfloat16, wmma::col_major> fbh[4], fbl[4];
#pragma unroll
    for (int i = 0; i < 2; i++) {
      wmma::load_matrix_sync(fah[i], &aH[(wm * 32 + i * 16) * ALD + kk], ALD);
      wmma::load_matrix_sync(fal[i], &aL[(wm * 32 + i * 16) * ALD + kk], ALD);
    }
#pragma unroll
    for (int j = 0; j < 4; j++) {
      wmma::load_matrix_sync(fbh[j], &bH[(wn * 64 + j * 16) * ALD + kk], ALD);
      wmma::load_matrix_sync(fbl[j], &bL[(wn * 64 + j * 16) * ALD + kk], ALD);
    }
#pragma unroll
    for (int i = 0; i < 2; i++)
#pragma unroll
      for (int j = 0; j < 4; j++) {
        wmma::mma_sync(acc[i][j], fah[i], fbh[j], acc[i][j]);
        wmma::mma_sync(acc[i][j], fah[i], fbl[j], acc[i][j]);
        wmma::mma_sync(acc[i][j], fal[i], fbh[j], acc[i][j]);
      }
  }

  // stage fp32 -> convert -> coalesced fp16 stores (2 passes of 64 rows)
  float* Cs = reinterpret_cast<float*>(psm);  // 64 x 128 fp32 = 32 KB
#pragma unroll
  for (int i = 0; i < 2; i++) {
    __syncthreads();
#pragma unroll
    for (int j = 0; j < 4; j++)
      wmma::store_matrix_sync(&Cs[(wm * 16) * 128 + wn * 64 + j * 16],
                              acc[i][j], 128, wmma::mem_row_major);
    __syncthreads();
#pragma unroll
    for (int it = 0; it < 4; it++) {
      const int e = tid + it * 256;      // 0..1023
      const int rs = e >> 4;             // staging row 0..63
      const int c8 = (e & 15) * 8;       // col 0..120
      const float* src = &Cs[rs * 128 + c8];
      __half h8[8];
#pragma unroll
      for (int x = 0; x < 8; x++) h8[x] = __float2half(src[x]);
      const int grow = (rs >> 4) * 32 + i * 16 + (rs & 15);
      *reinterpret_cast<uint4*>(
          &g_P[((size_t)bz * T_ + t0 + grow) * T_ + j0 + c8]) =
          *reinterpret_cast<const uint4*>(h8);
    }
  }
}

// =====================================================================
// Flash-style fused: content score + shift(P, fp16) + online softmax + AV.
// (scalar f32x2 version, validated rounds 3/6; P reads now fp16,
//  ctx stores now emit bf16 hi/lo splits directly)
// =====================================================================
__global__ __launch_bounds__(256) void flash_kernel(const float* __restrict__ ubias) {
  __shared__ float Qs[32 * 68];
  __shared__ float Ks[32 * 68];
  __shared__ float Vs[64 * 36];
  __shared__ float Ps[64 * 68];
  __shared__ float rowX[64];

  const int tid = threadIdx.x;
  const int bz = blockIdx.y, b = bz >> 4, h = bz & 15;
  const int t0 = blockIdx.x * 64;

#pragma unroll
  for (int r = 0; r < 2; r++) {
    int idx = tid + r * 256;
    int t = idx >> 3, kq = (idx & 7) * 4;
    float4 q4 = *reinterpret_cast<const float4*>(
        &g_qh[(size_t)(b * T_ + t0 + t) * D_ + h * DH_ + kq]);
    float4 u4 = *reinterpret_cast<const float4*>(&ubias[h * DH_ + kq]);
    Qs[(kq + 0) * 68 + t] = q4.x + u4.x;
    Qs[(kq + 1) * 68 + t] = q4.y + u4.y;
    Qs[(kq + 2) * 68 + t] = q4.z + u4.z;
    Qs[(kq + 3) * 68 + t] = q4.w + u4.w;
  }

  const int tx = tid & 15, ty = tid >> 4;
  const int dhg = tid & 7, rg = tid >> 3;
  const float isd = 0.04419417382415922f;

  float m_st[4], l_st[4];
#pragma unroll
  for (int i = 0; i < 4; i++) { m_st[i] = -3.4e38f; l_st[i] = 0.f; }
  u64 o00 = 0ull, o01 = 0ull, o10 = 0ull, o11 = 0ull;

  for (int c = 0; c < 16; c++) {
    const int s0 = c * 64;
#pragma unroll
    for (int r = 0; r < 2; r++) {
      int idx = tid + r * 256;
      int s = idx >> 3, kq = (idx & 7) * 4;
      const size_t gidx = (size_t)(b * T_ + s0 + s) * D_ + h * DH_ + kq;
      float4 k4 = *reinterpret_cast<const float4*>(&g_kh[gidx]);
      Ks[(kq + 0) * 68 + s] = k4.x; Ks[(kq + 1) * 68 + s] = k4.y;
      Ks[(kq + 2) * 68 + s] = k4.z; Ks[(kq + 3) * 68 + s] = k4.w;
      *reinterpret_cast<float4*>(&Vs[s * 36 + kq]) =
          *reinterpret_cast<const float4*>(&g_vh[gidx]);
    }
    __syncthreads();

    u64 acc[4][2];
#pragma unroll
    for (int i = 0; i < 4; i++) { acc[i][0] = 0ull; acc[i][1] = 0ull; }
#pragma unroll
    for (int kk = 0; kk < 32; kk++) {
      float4 a4 = *reinterpret_cast<const float4*>(&Qs[kk * 68 + ty * 4]);
      ulonglong2 b2 = *reinterpret_cast<const ulonglong2*>(&Ks[kk * 68 + tx * 4]);
      u64 a0 = pack2(a4.x, a4.x), a1 = pack2(a4.y, a4.y);
      u64 a2 = pack2(a4.z, a4.z), a3 = pack2(a4.w, a4.w);
      fma2(acc[0][0], a0, b2.x); fma2(acc[0][1], a0, b2.y);
      fma2(acc[1][0], a1, b2.x); fma2(acc[1][1], a1, b2.y);
      fma2(acc[2][0], a2, b2.x); fma2(acc[2][1], a2, b2.y);
      fma2(acc[3][0], a3, b2.x); fma2(acc[3][1], a3, b2.y);
    }

#pragma unroll
    for (int i = 0; i < 4; i++) {
      const int trow = ty * 4 + i;
      const int t = t0 + trow;
      const size_t rowb = ((size_t)bz * T_ + t) * T_;
      float2 lo = unpack2(acc[i][0]), hi = unpack2(acc[i][1]);
      float v[4] = {lo.x, lo.y, hi.x, hi.y};
#pragma unroll
      for (int j = 0; j < 4; j++) {
        const int s = s0 + tx * 4 + j;
        float pv;
        if (s <= t)          pv = __half2float(g_P[rowb + (s - t + (T_ - 1))]);
        else if (s == t + 1) pv = 0.f;
        else                 pv = __half2float(g_P[rowb + T_ + (s - t - 2)]);
        v[j] = (v[j] + pv) * isd;
      }
      float mc = fmaxf(fmaxf(v[0], v[1]), fmaxf(v[2], v[3]));
#pragma unroll
      for (int o = 8; o > 0; o >>= 1) mc = fmaxf(mc, __shfl_xor_sync(0xffffffffu, mc, o));
      const float m_new = fmaxf(m_st[i], mc);
      const float al = __expf(m_st[i] - m_new);
      float p0 = __expf(v[0] - m_new), p1 = __expf(v[1] - m_new);
      float p2 = __expf(v[2] - m_new), p3 = __expf(v[3] - m_new);
      float rs = (p0 + p1) + (p2 + p3);
#pragma unroll
      for (int o = 8; o > 0; o >>= 1) rs += __shfl_xor_sync(0xffffffffu, rs, o);
      l_st[i] = l_st[i] * al + rs;
      m_st[i] = m_new;
      *reinterpret_cast<float4*>(&Ps[trow * 68 + tx * 4]) =
          make_float4(p0, p1, p2, p3);
      if (tx == 0) rowX[trow] = al;
    }
    __syncthreads();

    {
      const float a0 = rowX[rg * 2], a1 = rowX[rg * 2 + 1];
      const u64 pa0 = pack2(a0, a0), pa1 = pack2(a1, a1);
      mul2(o00, pa0); mul2(o01, pa0);
      mul2(o10, pa1); mul2(o11, pa1);
      const float* rA = &Ps[(rg * 2) * 68];
      const float* rB = rA + 68;
#pragma unroll 4
      for (int ss = 0; ss < 64; ss += 4) {
        float4 pa = *reinterpret_cast<const float4*>(&rA[ss]);
        float4 pb = *reinterpret_cast<const float4*>(&rB[ss]);
        ulonglong2 v0 = *reinterpret_cast<const ulonglong2*>(&Vs[(ss + 0) * 36 + dhg * 4]);
        ulonglong2 v1 = *reinterpret_cast<const ulonglong2*>(&Vs[(ss + 1) * 36 + dhg * 4]);
        ulonglong2 v2 = *reinterpret_cast<const ulonglong2*>(&Vs[(ss + 2) * 36 + dhg * 4]);
        ulonglong2 v3 = *reinterpret_cast<const ulonglong2*>(&Vs[(ss + 3) * 36 + dhg * 4]);
        fma2(o00, pack2(pa.x, pa.x), v0.x); fma2(o01, pack2(pa.x, pa.x), v0.y);
        fma2(o10, pack2(pb.x, pb.x), v0.x); fma2(o11, pack2(pb.x, pb.x), v0.y);
        fma2(o00, pack2(pa.y, pa.y), v1.x); fma2(o01, pack2(pa.y, pa.y), v1.y);
        fma2(o10, pack2(pb.y, pb.y), v1.x); fma2(o11, pack2(pb.y, pb.y), v1.y);
        fma2(o00, pack2(pa.z, pa.z), v2.x); fma2(o01, pack2(pa.z, pa.z), v2.y);
        fma2(o10, pack2(pb.z, pb.z), v2.x); fma2(o11, pack2(pb.z, pb.z), v2.y);
        fma2(o00, pack2(pa.w, pa.w), v3.x); fma2(o01, pack2(pa.w, pa.w), v3.y);
        fma2(o10, pack2(pb.w, pb.w), v3.x); fma2(o11, pack2(pb.w, pb.w), v3.y);
      }
    }
    __syncthreads();
  }

  if (tx == 0) {
#pragma unroll
    for (int i = 0; i < 4; i++) rowX[ty * 4 + i] = 1.0f / l_st[i];
  }
  __syncthreads();
  {
    const float n0 = rowX[rg * 2], n1 = rowX[rg * 2 + 1];
    float2 x0 = unpack2(o00), x1 = unpack2(o01);
    float2 y0 = unpack2(o10), y1 = unpack2(o11);
    float4 r0 = make_float4(x0.x * n0, x0.y * n0, x1.x * n0, x1.y * n0);
    float4 r1 = make_float4(y0.x * n1, y0.y * n1, y1.x * n1, y1.y * n1);
    const size_t base = (size_t)(b * T_ + t0 + rg * 2) * D_ + h * DH_ + dhg * 4;
    split_store4(r0, g_ctxh, g_ctxl, base);
    split_store4(r1, g_ctxh, g_ctxl, base + D_);
  }
}

// =====================================================================
extern "C" void kernel_launch(void* const* d_in, const int* in_sizes, int n_in,
                              void* d_out, int out_size) {
  const float* q   = (const float*)d_in[0];
  const float* k   = (const float*)d_in[1];
  const float* v   = (const float*)d_in[2];
  const float* pos = (const float*)d_in[3];
  const float* Wq  = (const float*)d_in[4];
  const float* bq  = (const float*)d_in[5];
  const float* Wp  = (const float*)d_in[6];
  const float* Wf  = (const float*)d_in[7];
  const float* bf  = (const float*)d_in[8];
  const float* ub  = (const float*)d_in[9];
  const float* vb  = (const float*)d_in[10];
  float* out = (float*)d_out;

  convert_inputs_kernel<<<dim3(BT_ * D_ / 1024, 4), 256>>>(q, k, v, pos);
  convert_w_kernel<<<dim3(16, 16, 3), 256>>>(Wq, Wp, Wf);

  wmma_proj_kernel<<<dim3(8, 32, 4), 256>>>(bq, ub, vb);

  wmma_pscore_kernel<<<dim3(8, 8, 64), 256>>>();

  flash_kernel<<<dim3(16, 64), 256>>>(ub);

  wmma_final_kernel<<<dim3(8, 32), 256>>>(bf, out);
}

// round 13
// speedup vs baseline: 1.3807x; 1.0662x over previous
#include <cuda_runtime.h>
#include <cuda_bf16.h>
#include <cuda_fp16.h>
#include <mma.h>
#include <cstddef>
#include <cstdint>

using namespace nvcuda;

#define B_ 4
#define T_ 1024
#define D_ 512
#define H_ 16
#define DH_ 32
#define BT_ (B_ * T_)

typedef unsigned long long u64;

// ---- f32x2 packed-math helpers (sm_103a) ----
__device__ __forceinline__ u64 pack2(float x, float y) {
  u64 r; asm("mov.b64 %0, {%1, %2};" : "=l"(r) : "f"(x), "f"(y)); return r;
}
__device__ __forceinline__ void fma2(u64& d, u64 a, u64 b) {
  asm("fma.rn.f32x2 %0, %1, %2, %0;" : "+l"(d) : "l"(a), "l"(b));
}
__device__ __forceinline__ float2 unpack2(u64 v) {
  float2 f; asm("mov.b64 {%0, %1}, %2;" : "=f"(f.x), "=f"(f.y) : "l"(v)); return f;
}

// ---- scratch (static device globals; no runtime allocation) ----
__device__ float g_qh[BT_ * D_];
__device__ float g_kh[BT_ * D_];
__device__ float g_vh[BT_ * D_];
__device__ __half g_P[(size_t)B_ * H_ * T_ * T_];  // 128 MB, unshifted pos scores

__device__ __nv_bfloat16 g_inh[4 * BT_ * D_];   // hi(q,k,v,pos)
__device__ __nv_bfloat16 g_inl[4 * BT_ * D_];   // lo
__device__ __nv_bfloat16 g_wth[3 * D_ * D_];    // hi(Wq^T, Wp^T, Wf^T)  [n][k]
__device__ __nv_bfloat16 g_wtl[3 * D_ * D_];
__device__ __nv_bfloat16 g_ctxh[BT_ * D_];
__device__ __nv_bfloat16 g_ctxl[BT_ * D_];
__device__ __nv_bfloat16 g_aqh[BT_ * D_];       // hi(qh + v_bias)
__device__ __nv_bfloat16 g_aql[BT_ * D_];
__device__ __nv_bfloat16 g_phh[BT_ * D_];       // hi(ph)
__device__ __nv_bfloat16 g_phl[BT_ * D_];

// =====================================================================
// fp32 -> bf16 hi/lo split
// =====================================================================
__device__ __forceinline__ void split_bf16(float x, __nv_bfloat16& h, __nv_bfloat16& l) {
  h = __float2bfloat16(x);
  l = __float2bfloat16(x - __bfloat162float(h));
}

__device__ __forceinline__ void split_store4(float4 x, __nv_bfloat16* Hh,
                                             __nv_bfloat16* Ll, size_t i) {
  __nv_bfloat162 h0, h1, l0, l1;
  split_bf16(x.x, h0.x, l0.x); split_bf16(x.y, h0.y, l0.y);
  split_bf16(x.z, h1.x, l1.x); split_bf16(x.w, h1.y, l1.y);
  *reinterpret_cast<__nv_bfloat162*>(&Hh[i]) = h0;
  *reinterpret_cast<__nv_bfloat162*>(&Hh[i + 2]) = h1;
  *reinterpret_cast<__nv_bfloat162*>(&Ll[i]) = l0;
  *reinterpret_cast<__nv_bfloat162*>(&Ll[i + 2]) = l1;
}

__global__ __launch_bounds__(256) void convert_inputs_kernel(
    const float* __restrict__ q, const float* __restrict__ k,
    const float* __restrict__ v, const float* __restrict__ pos) {
  const int z = blockIdx.y;
  const float* src = (z == 0) ? q : (z == 1) ? k : (z == 2) ? v : pos;
  const size_t i = ((size_t)blockIdx.x * 256 + threadIdx.x) * 4;
  split_store4(*reinterpret_cast<const float4*>(&src[i]),
               g_inh + (size_t)z * BT_ * D_, g_inl + (size_t)z * BT_ * D_, i);
}

// W [k][n] -> Wt [n][k] hi/lo bf16 (32x32 smem tile transpose)
__global__ __launch_bounds__(256) void convert_w_kernel(
    const float* __restrict__ Wq, const float* __restrict__ Wp,
    const float* __restrict__ Wf) {
  const int z = blockIdx.z;
  const float* W = (z == 0) ? Wq : (z == 1) ? Wp : Wf;
  __nv_bfloat16* Hh = g_wth + (size_t)z * D_ * D_;
  __nv_bfloat16* Ll = g_wtl + (size_t)z * D_ * D_;
  __shared__ float tile[32][33];
  const int tx = threadIdx.x & 31, ty = threadIdx.x >> 5;
  const int k0 = blockIdx.y * 32, n0 = blockIdx.x * 32;
#pragma unroll
  for (int r = 0; r < 4; r++)
    tile[ty + 8 * r][tx] = W[(size_t)(k0 + ty + 8 * r) * D_ + n0 + tx];
  __syncthreads();
#pragma unroll
  for (int r = 0; r < 4; r++) {
    const int n = n0 + ty + 8 * r;
    float x = tile[tx][ty + 8 * r];
    __nv_bfloat16 h, l; split_bf16(x, h, l);
    Hh[(size_t)n * D_ + k0 + tx] = h;
    Ll[(size_t)n * D_ + k0 + tx] = l;
  }
}

// =====================================================================
// wmma split-bf16 GEMM (validated round 6) with fused split epilogues.
// mode: 0=q (fp32 qh + aq split), 1=kh fp32, 2=vh fp32,
//       3=ph splits only, 4=final (fp32 out + bias)
// =====================================================================
#define ALD 40

__device__ __forceinline__ void wmma_gemm_body(
    const __nv_bfloat16* __restrict__ Ah, const __nv_bfloat16* __restrict__ Al,
    const __nv_bfloat16* __restrict__ Bh, const __nv_bfloat16* __restrict__ Bl,
    const float* __restrict__ bias, float* __restrict__ C, int m0, int n0,
    int mode, const float* __restrict__ vb) {
  __shared__ __align__(16) char smraw[32768];
  __nv_bfloat16* aH = reinterpret_cast<__nv_bfloat16*>(smraw);
  __nv_bfloat16* aL = aH + 128 * ALD;
  __nv_bfloat16* bH = aL + 128 * ALD;
  __nv_bfloat16* bL = bH + 64 * ALD;

  const int tid = threadIdx.x;
  const int wid = tid >> 5;
  const int wm = wid >> 1, wn = wid & 1;

  wmma::fragment<wmma::accumulator, 16, 16, 16, float> acc[2][2];
#pragma unroll
  for (int i = 0; i < 2; i++)
#pragma unroll
    for (int j = 0; j < 2; j++) wmma::fill_fragment(acc[i][j], 0.f);

  for (int k0 = 0; k0 < 512; k0 += 32) {
#pragma unroll
    for (int r2 = 0; r2 < 2; r2++) {
      const int idx = tid + r2 * 256;
      const int r = idx >> 2, c8 = (idx & 3) * 8;
      const size_t g = (size_t)(m0 + r) * D_ + k0 + c8;
      *reinterpret_cast<uint4*>(&aH[r * ALD + c8]) = *reinterpret_cast<const uint4*>(&Ah[g]);
      *reinterpret_cast<uint4*>(&aL[r * ALD + c8]) = *reinterpret_cast<const uint4*>(&Al[g]);
    }
    {
      const int r = tid >> 2, c8 = (tid & 3) * 8;
      const size_t g = (size_t)(n0 + r) * D_ + k0 + c8;
      *reinterpret_cast<uint4*>(&bH[r * ALD + c8]) = *reinterpret_cast<const uint4*>(&Bh[g]);
      *reinterpret_cast<uint4*>(&bL[r * ALD + c8]) = *reinterpret_cast<const uint4*>(&Bl[g]);
    }
    __syncthreads();
#pragma unroll
    for (int kk = 0; kk < 32; kk += 16) {
      wmma::fragment<wmma::matrix_a, 16, 16, 16, __nv_bfloat16, wmma::row_major> fah[2], fal[2];
      wmma::fragment<wmma::matrix_b, 16, 16, 16, __nv_bfloat16, wmma::col_major> fbh[2], fbl[2];
#pragma unroll
      for (int i = 0; i < 2; i++) {
        wmma::load_matrix_sync(fah[i], &aH[(wm * 32 + i * 16) * ALD + kk], ALD);
        wmma::load_matrix_sync(fal[i], &aL[(wm * 32 + i * 16) * ALD + kk], ALD);
        wmma::load_matrix_sync(fbh[i], &bH[(wn * 32 + i * 16) * ALD + kk], ALD);
        wmma::load_matrix_sync(fbl[i], &bL[(wn * 32 + i * 16) * ALD + kk], ALD);
      }
#pragma unroll
      for (int i = 0; i < 2; i++)
#pragma unroll
        for (int j = 0; j < 2; j++) {
          wmma::mma_sync(acc[i][j], fah[i], fbh[j], acc[i][j]);
          wmma::mma_sync(acc[i][j], fah[i], fbl[j], acc[i][j]);
          wmma::mma_sync(acc[i][j], fal[i], fbh[j], acc[i][j]);
        }
    }
    __syncthreads();
  }

  float* Cs = reinterpret_cast<float*>(smraw);
#pragma unroll
  for (int i = 0; i < 2; i++)
#pragma unroll
    for (int j = 0; j < 2; j++)
      wmma::store_matrix_sync(&Cs[(wm * 32 + i * 16) * 64 + wn * 32 + j * 16],
                              acc[i][j], 64, wmma::mem_row_major);
  __syncthreads();
#pragma unroll
  for (int r2 = 0; r2 < 8; r2++) {
    const int idx = tid + r2 * 256;
    const int row = idx >> 4, c4 = (idx & 15) * 4;
    float4 o = *reinterpret_cast<const float4*>(&Cs[row * 64 + c4]);
    if (bias) {
      float4 bb = *reinterpret_cast<const float4*>(&bias[n0 + c4]);
      o.x += bb.x; o.y += bb.y; o.z += bb.z; o.w += bb.w;
    }
    const size_t g = (size_t)(m0 + row) * D_ + n0 + c4;
    if (mode == 0) {
      *reinterpret_cast<float4*>(&g_qh[g]) = o;
      float4 vb4 = *reinterpret_cast<const float4*>(&vb[n0 + c4]);
      float4 aq = make_float4(o.x + vb4.x, o.y + vb4.y, o.z + vb4.z, o.w + vb4.w);
      split_store4(aq, g_aqh, g_aql, g);
    } else if (mode == 1) {
      *reinterpret_cast<float4*>(&g_kh[g]) = o;
    } else if (mode == 2) {
      *reinterpret_cast<float4*>(&g_vh[g]) = o;
    } else if (mode == 3) {
      split_store4(o, g_phh, g_phl, g);
    } else {
      *reinterpret_cast<float4*>(&C[g]) = o;
    }
  }
}

__global__ __launch_bounds__(256) void wmma_proj_kernel(
    const float* __restrict__ bq, const float* __restrict__ vb) {
  const int z = blockIdx.z;
  const __nv_bfloat16* Ah = g_inh + (size_t)z * BT_ * D_;
  const __nv_bfloat16* Al = g_inl + (size_t)z * BT_ * D_;
  const int ws = (z < 3) ? 0 : 1;
  wmma_gemm_body(Ah, Al, g_wth + (size_t)ws * D_ * D_, g_wtl + (size_t)ws * D_ * D_,
                 (z < 3) ? bq : nullptr, nullptr, blockIdx.y * 128, blockIdx.x * 64,
                 z, vb);
}

__global__ __launch_bounds__(256) void wmma_final_kernel(const float* __restrict__ bf,
                                                         float* __restrict__ out) {
  wmma_gemm_body(g_ctxh, g_ctxl, g_wth + (size_t)2 * D_ * D_, g_wtl + (size_t)2 * D_ * D_,
                 bf, out, blockIdx.y * 128, blockIdx.x * 64, 4, nullptr);
}

// =====================================================================
// wmma pscore v2: block tile 128(t) x 64(j), K=32, 8 warps (4m x 2n),
// warp tile 32x32 -> acc[2][2] (low register pressure, 2 CTAs/SM).
// Output fp16 via one-pass 32 KB smem staging.
// =====================================================================
__global__ __launch_bounds__(256) void wmma_pscore_kernel() {
  __shared__ __align__(16) char psm[32768];
  __nv_bfloat16* aH = reinterpret_cast<__nv_bfloat16*>(psm);
  __nv_bfloat16* aL = aH + 128 * ALD;
  __nv_bfloat16* bH = aL + 128 * ALD;
  __nv_bfloat16* bL = bH + 64 * ALD;

  const int tid = threadIdx.x;
  const int wid = tid >> 5;
  const int wm = wid >> 1, wn = wid & 1;
  const int bz = blockIdx.z, b = bz >> 4, h = bz & 15;
  const int t0 = blockIdx.y * 128, j0 = blockIdx.x * 64;

  // A: aq rows t0..t0+127 (2 units/thread); B: ph rows j0..j0+63 (1 unit/thread)
#pragma unroll
  for (int r2 = 0; r2 < 2; r2++) {
    const int idx = tid + r2 * 256;
    const int r = idx >> 2, c8 = (idx & 3) * 8;
    const size_t ga = (size_t)(b * T_ + t0 + r) * D_ + h * DH_ + c8;
    *reinterpret_cast<uint4*>(&aH[r * ALD + c8]) = *reinterpret_cast<const uint4*>(&g_aqh[ga]);
    *reinterpret_cast<uint4*>(&aL[r * ALD + c8]) = *reinterpret_cast<const uint4*>(&g_aql[ga]);
  }
  {
    const int r = tid >> 2, c8 = (tid & 3) * 8;
    const size_t gb = (size_t)(b * T_ + j0 + r) * D_ + h * DH_ + c8;
    *reinterpret_cast<uint4*>(&bH[r * ALD + c8]) = *reinterpret_cast<const uint4*>(&g_phh[gb]);
    *reinterpret_cast<uint4*>(&bL[r * ALD + c8]) = *reinterpret_cast<const uint4*>(&g_phl[gb]);
  }
  __syncthreads();

  wmma::fragment<wmma::accumulator, 16, 16, 16, float> acc[2][2];
#pragma unroll
  for (int i = 0; i < 2; i++)
#pragma unroll
    for (int j = 0; j < 2; j++) wmma::fill_fragment(acc[i][j], 0.f);

#pragma unroll
  for (int kk = 0; kk < 32; kk += 16) {
    wmma::fragment<wmma::matrix_a, 16, 16, 16, __nv_bfloat16, wmma::row_major> fah[2], fal[2];
    wmma::fragment<wmma::matrix_b, 16, 16, 16, __nv_bfloat16, wmma::col_major> fbh[2], fbl[2];
#pragma unroll
    for (int i = 0; i < 2; i++) {
      wmma::load_matrix_sync(fah[i], &aH[(wm * 32 + i * 16) * ALD + kk], ALD);
      wmma::load_matrix_sync(fal[i], &aL[(wm * 32 + i * 16) * ALD + kk], ALD);
      wmma::load_matrix_sync(fbh[i], &bH[(wn * 32 + i * 16) * ALD + kk], ALD);
      wmma::load_matrix_sync(fbl[i], &bL[(wn * 32 + i * 16) * ALD + kk], ALD);
    }
#pragma unroll
    for (int i = 0; i < 2; i++)
#pragma unroll
      for (int j = 0; j < 2; j++) {
        wmma::mma_sync(acc[i][j], fah[i], fbh[j], acc[i][j]);
        wmma::mma_sync(acc[i][j], fah[i], fbl[j], acc[i][j]);
        wmma::mma_sync(acc[i][j], fal[i], fbh[j], acc[i][j]);
      }
  }

  // one-pass staging: 128 x 64 fp32 (32 KB), then coalesced fp16 stores
  __syncthreads();
  float* Cs = reinterpret_cast<float*>(psm);
#pragma unroll
  for (int i = 0; i < 2; i++)
#pragma unroll
    for (int j = 0; j < 2; j++)
      wmma::store_matrix_sync(&Cs[(wm * 32 + i * 16) * 64 + wn * 32 + j * 16],
                              acc[i][j], 64, wmma::mem_row_major);
  __syncthreads();
#pragma unroll
  for (int it = 0; it < 4; it++) {
    const int e = tid + it * 256;   // 0..1023
    const int rs = e >> 3;          // row 0..127
    const int c8 = (e & 7) * 8;     // col 0..56
    const float* src = &Cs[rs * 64 + c8];
    __half h8[8];
#pragma unroll
    for (int x = 0; x < 8; x++) h8[x] = __float2half(src[x]);
    *reinterpret_cast<uint4*>(
        &g_P[((size_t)bz * T_ + t0 + rs) * T_ + j0 + c8]) =
        *reinterpret_cast<const uint4*>(h8);
  }
}

// =====================================================================
// Flash-style fused: content score + shift(P, fp16) + softmax + AV.
// v3: NO online max (scores are O(1): shift-invariant softmax, fp32 exp
// cannot overflow) -> no per-chunk shuffles, no alpha rescale, no rowX
// traffic in the loop. Row sums in 4 registers; one xor-16 reduce at end.
// =====================================================================
__global__ __launch_bounds__(256) void flash_kernel(const float* __restrict__ ubias) {
  __shared__ float Qs[32 * 68];
  __shared__ float Ks[32 * 68];
  __shared__ float Vs[64 * 36];
  __shared__ float Ps[64 * 68];
  __shared__ float rowX[64];

  const int tid = threadIdx.x;
  const int bz = blockIdx.y, b = bz >> 4, h = bz & 15;
  const int t0 = blockIdx.x * 64;

#pragma unroll
  for (int r = 0; r < 2; r++) {
    int idx = tid + r * 256;
    int t = idx >> 3, kq = (idx & 7) * 4;
    float4 q4 = *reinterpret_cast<const float4*>(
        &g_qh[(size_t)(b * T_ + t0 + t) * D_ + h * DH_ + kq]);
    float4 u4 = *reinterpret_cast<const float4*>(&ubias[h * DH_ + kq]);
    Qs[(kq + 0) * 68 + t] = q4.x + u4.x;
    Qs[(kq + 1) * 68 + t] = q4.y + u4.y;
    Qs[(kq + 2) * 68 + t] = q4.z + u4.z;
    Qs[(kq + 3) * 68 + t] = q4.w + u4.w;
  }

  const int tx = tid & 15, ty = tid >> 4;
  const int dhg = tid & 7, rg = tid >> 3;
  const float isd = 0.04419417382415922f;

  float lsum[4] = {0.f, 0.f, 0.f, 0.f};
  u64 o00 = 0ull, o01 = 0ull, o10 = 0ull, o11 = 0ull;

  for (int c = 0; c < 16; c++) {
    const int s0 = c * 64;
#pragma unroll
    for (int r = 0; r < 2; r++) {
      int idx = tid + r * 256;
      int s = idx >> 3, kq = (idx & 7) * 4;
      const size_t gidx = (size_t)(b * T_ + s0 + s) * D_ + h * DH_ + kq;
      float4 k4 = *reinterpret_cast<const float4*>(&g_kh[gidx]);
      Ks[(kq + 0) * 68 + s] = k4.x; Ks[(kq + 1) * 68 + s] = k4.y;
      Ks[(kq + 2) * 68 + s] = k4.z; Ks[(kq + 3) * 68 + s] = k4.w;
      *reinterpret_cast<float4*>(&Vs[s * 36 + kq]) =
          *reinterpret_cast<const float4*>(&g_vh[gidx]);
    }
    __syncthreads();

    u64 acc[4][2];
#pragma unroll
    for (int i = 0; i < 4; i++) { acc[i][0] = 0ull; acc[i][1] = 0ull; }
#pragma unroll
    for (int kk = 0; kk < 32; kk++) {
      float4 a4 = *reinterpret_cast<const float4*>(&Qs[kk * 68 + ty * 4]);
      ulonglong2 b2 = *reinterpret_cast<const ulonglong2*>(&Ks[kk * 68 + tx * 4]);
      u64 a0 = pack2(a4.x, a4.x), a1 = pack2(a4.y, a4.y);
      u64 a2 = pack2(a4.z, a4.z), a3 = pack2(a4.w, a4.w);
      fma2(acc[0][0], a0, b2.x); fma2(acc[0][1], a0, b2.y);
      fma2(acc[1][0], a1, b2.x); fma2(acc[1][1], a1, b2.y);
      fma2(acc[2][0], a2, b2.x); fma2(acc[2][1], a2, b2.y);
      fma2(acc[3][0], a3, b2.x); fma2(acc[3][1], a3, b2.y);
    }

#pragma unroll
    for (int i = 0; i < 4; i++) {
      const int trow = ty * 4 + i;
      const int t = t0 + trow;
      const size_t rowb = ((size_t)bz * T_ + t) * T_;
      float2 lo = unpack2(acc[i][0]), hi = unpack2(acc[i][1]);
      float v[4] = {lo.x, lo.y, hi.x, hi.y};
#pragma unroll
      for (int j = 0; j < 4; j++) {
        const int s = s0 + tx * 4 + j;
        float pv;
        if (s <= t)          pv = __half2float(g_P[rowb + (s - t + (T_ - 1))]);
        else if (s == t + 1) pv = 0.f;
        else                 pv = __half2float(g_P[rowb + T_ + (s - t - 2)]);
        v[j] = __expf((v[j] + pv) * isd);
      }
      lsum[i] += (v[0] + v[1]) + (v[2] + v[3]);
      *reinterpret_cast<float4*>(&Ps[trow * 68 + tx * 4]) =
          make_float4(v[0], v[1], v[2], v[3]);
    }
    __syncthreads();

    {
      const float* rA = &Ps[(rg * 2) * 68];
      const float* rB = rA + 68;
#pragma unroll 4
      for (int ss = 0; ss < 64; ss += 4) {
        float4 pa = *reinterpret_cast<const float4*>(&rA[ss]);
        float4 pb = *reinterpret_cast<const float4*>(&rB[ss]);
        ulonglong2 v0 = *reinterpret_cast<const ulonglong2*>(&Vs[(ss + 0) * 36 + dhg * 4]);
        ulonglong2 v1 = *reinterpret_cast<const ulonglong2*>(&Vs[(ss + 1) * 36 + dhg * 4]);
        ulonglong2 v2 = *reinterpret_cast<const ulonglong2*>(&Vs[(ss + 2) * 36 + dhg * 4]);
        ulonglong2 v3 = *reinterpret_cast<const ulonglong2*>(&Vs[(ss + 3) * 36 + dhg * 4]);
        fma2(o00, pack2(pa.x, pa.x), v0.x); fma2(o01, pack2(pa.x, pa.x), v0.y);
        fma2(o10, pack2(pb.x, pb.x), v0.x); fma2(o11, pack2(pb.x, pb.x), v0.y);
        fma2(o00, pack2(pa.y, pa.y), v1.x); fma2(o01, pack2(pa.y, pa.y), v1.y);
        fma2(o10, pack2(pb.y, pb.y), v1.x); fma2(o11, pack2(pb.y, pb.y), v1.y);
        fma2(o00, pack2(pa.z, pa.z), v2.x); fma2(o01, pack2(pa.z, pa.z), v2.y);
        fma2(o10, pack2(pb.z, pb.z), v2.x); fma2(o11, pack2(pb.z, pb.z), v2.y);
        fma2(o00, pack2(pa.w, pa.w), v3.x); fma2(o01, pack2(pa.w, pa.w), v3.y);
        fma2(o10, pack2(pb.w, pb.w), v3.x); fma2(o11, pack2(pb.w, pb.w), v3.y);
      }
    }
    __syncthreads();
  }

  // row-sum reduction across the 16 tx lanes sharing each row
#pragma unroll
  for (int i = 0; i < 4; i++) {
    float l = lsum[i];
    l += __shfl_xor_sync(0xffffffffu, l, 1);
    l += __shfl_xor_sync(0xffffffffu, l, 2);
    l += __shfl_xor_sync(0xffffffffu, l, 4);
    l += __shfl_xor_sync(0xffffffffu, l, 8);
    if (tx == 0) rowX[ty * 4 + i] = 1.0f / l;
  }
  __syncthreads();
  {
    const float n0 = rowX[rg * 2], n1 = rowX[rg * 2 + 1];
    float2 x0 = unpack2(o00), x1 = unpack2(o01);
    float2 y0 = unpack2(o10), y1 = unpack2(o11);
    float4 r0 = make_float4(x0.x * n0, x0.y * n0, x1.x * n0, x1.y * n0);
    float4 r1 = make_float4(y0.x * n1, y0.y * n1, y1.x * n1, y1.y * n1);
    const size_t base = (size_t)(b * T_ + t0 + rg * 2) * D_ + h * DH_ + dhg * 4;
    split_store4(r0, g_ctxh, g_ctxl, base);
    split_store4(r1, g_ctxh, g_ctxl, base + D_);
  }
}

// =====================================================================
extern "C" void kernel_launch(void* const* d_in, const int* in_sizes, int n_in,
                              void* d_out, int out_size) {
  const float* q   = (const float*)d_in[0];
  const float* k   = (const float*)d_in[1];
  const float* v   = (const float*)d_in[2];
  const float* pos = (const float*)d_in[3];
  const float* Wq  = (const float*)d_in[4];
  const float* bq  = (const float*)d_in[5];
  const float* Wp  = (const float*)d_in[6];
  const float* Wf  = (const float*)d_in[7];
  const float* bf  = (const float*)d_in[8];
  const float* ub  = (const float*)d_in[9];
  const float* vb  = (const float*)d_in[10];
  float* out = (float*)d_out;

  convert_inputs_kernel<<<dim3(BT_ * D_ / 1024, 4), 256>>>(q, k, v, pos);
  convert_w_kernel<<<dim3(16, 16, 3), 256>>>(Wq, Wp, Wf);

  wmma_proj_kernel<<<dim3(8, 32, 4), 256>>>(bq, vb);

  wmma_pscore_kernel<<<dim3(16, 8, 64), 256>>>();

  flash_kernel<<<dim3(16, 64), 256>>>(ub);

  wmma_final_kernel<<<dim3(8, 32), 256>>>(bf, out);
}

// round 14
// speedup vs baseline: 1.4310x; 1.0364x over previous
#include <cuda_runtime.h>
#include <cuda_bf16.h>
#include <cuda_fp16.h>
#include <mma.h>
#include <cstddef>
#include <cstdint>

using namespace nvcuda;

#define B_ 4
#define T_ 1024
#define D_ 512
#define H_ 16
#define DH_ 32
#define BT_ (B_ * T_)

typedef unsigned long long u64;

// ---- f32x2 packed-math helpers (sm_103a) ----
__device__ __forceinline__ u64 pack2(float x, float y) {
  u64 r; asm("mov.b64 %0, {%1, %2};" : "=l"(r) : "f"(x), "f"(y)); return r;
}
__device__ __forceinline__ void fma2(u64& d, u64 a, u64 b) {
  asm("fma.rn.f32x2 %0, %1, %2, %0;" : "+l"(d) : "l"(a), "l"(b));
}
__device__ __forceinline__ float2 unpack2(u64 v) {
  float2 f; asm("mov.b64 {%0, %1}, %2;" : "=f"(f.x), "=f"(f.y) : "l"(v)); return f;
}

// ---- scratch (static device globals; no runtime allocation) ----
__device__ float g_qh[BT_ * D_];
__device__ float g_kh[BT_ * D_];
__device__ __half g_P[(size_t)B_ * H_ * T_ * T_];  // 128 MB, unshifted pos scores

__device__ __nv_bfloat16 g_inh[4 * BT_ * D_];   // hi(q,k,v,pos)
__device__ __nv_bfloat16 g_inl[4 * BT_ * D_];   // lo
__device__ __nv_bfloat16 g_wth[3 * D_ * D_];    // hi(Wq^T, Wp^T, Wf^T)  [n][k]
__device__ __nv_bfloat16 g_wtl[3 * D_ * D_];
__device__ __nv_bfloat16 g_ctxh[BT_ * D_];
__device__ __nv_bfloat16 g_ctxl[BT_ * D_];
__device__ __nv_bfloat16 g_aqh[BT_ * D_];       // hi(qh + v_bias)
__device__ __nv_bfloat16 g_aql[BT_ * D_];
__device__ __nv_bfloat16 g_phh[BT_ * D_];       // hi(ph)
__device__ __nv_bfloat16 g_phl[BT_ * D_];
__device__ __nv_bfloat16 g_vhh[BT_ * D_];       // hi(vh)
__device__ __nv_bfloat16 g_vhl[BT_ * D_];

// =====================================================================
// fp32 -> bf16 hi/lo split
// =====================================================================
__device__ __forceinline__ void split_bf16(float x, __nv_bfloat16& h, __nv_bfloat16& l) {
  h = __float2bfloat16(x);
  l = __float2bfloat16(x - __bfloat162float(h));
}

__device__ __forceinline__ void split_store4(float4 x, __nv_bfloat16* Hh,
                                             __nv_bfloat16* Ll, size_t i) {
  __nv_bfloat162 h0, h1, l0, l1;
  split_bf16(x.x, h0.x, l0.x); split_bf16(x.y, h0.y, l0.y);
  split_bf16(x.z, h1.x, l1.x); split_bf16(x.w, h1.y, l1.y);
  *reinterpret_cast<__nv_bfloat162*>(&Hh[i]) = h0;
  *reinterpret_cast<__nv_bfloat162*>(&Hh[i + 2]) = h1;
  *reinterpret_cast<__nv_bfloat162*>(&Ll[i]) = l0;
  *reinterpret_cast<__nv_bfloat162*>(&Ll[i + 2]) = l1;
}

__global__ __launch_bounds__(256) void convert_inputs_kernel(
    const float* __restrict__ q, const float* __restrict__ k,
    const float* __restrict__ v, const float* __restrict__ pos) {
  const int z = blockIdx.y;
  const float* src = (z == 0) ? q : (z == 1) ? k : (z == 2) ? v : pos;
  const size_t i = ((size_t)blockIdx.x * 256 + threadIdx.x) * 4;
  split_store4(*reinterpret_cast<const float4*>(&src[i]),
               g_inh + (size_t)z * BT_ * D_, g_inl + (size_t)z * BT_ * D_, i);
}

// W [k][n] -> Wt [n][k] hi/lo bf16 (32x32 smem tile transpose)
__global__ __launch_bounds__(256) void convert_w_kernel(
    const float* __restrict__ Wq, const float* __restrict__ Wp,
    const float* __restrict__ Wf) {
  const int z = blockIdx.z;
  const float* W = (z == 0) ? Wq : (z == 1) ? Wp : Wf;
  __nv_bfloat16* Hh = g_wth + (size_t)z * D_ * D_;
  __nv_bfloat16* Ll = g_wtl + (size_t)z * D_ * D_;
  __shared__ float tile[32][33];
  const int tx = threadIdx.x & 31, ty = threadIdx.x >> 5;
  const int k0 = blockIdx.y * 32, n0 = blockIdx.x * 32;
#pragma unroll
  for (int r = 0; r < 4; r++)
    tile[ty + 8 * r][tx] = W[(size_t)(k0 + ty + 8 * r) * D_ + n0 + tx];
  __syncthreads();
#pragma unroll
  for (int r = 0; r < 4; r++) {
    const int n = n0 + ty + 8 * r;
    float x = tile[tx][ty + 8 * r];
    __nv_bfloat16 h, l; split_bf16(x, h, l);
    Hh[(size_t)n * D_ + k0 + tx] = h;
    Ll[(size_t)n * D_ + k0 + tx] = l;
  }
}

// =====================================================================
// wmma split-bf16 GEMM (validated round 6) with fused split epilogues.
// mode: 0=q (fp32 qh + aq split), 1=kh fp32, 2=vh splits,
//       3=ph splits only, 4=final (fp32 out + bias)
// =====================================================================
#define ALD 40

__device__ __forceinline__ void wmma_gemm_body(
    const __nv_bfloat16* __restrict__ Ah, const __nv_bfloat16* __restrict__ Al,
    const __nv_bfloat16* __restrict__ Bh, const __nv_bfloat16* __restrict__ Bl,
    const float* __restrict__ bias, float* __restrict__ C, int m0, int n0,
    int mode, const float* __restrict__ vb) {
  __shared__ __align__(16) char smraw[32768];
  __nv_bfloat16* aH = reinterpret_cast<__nv_bfloat16*>(smraw);
  __nv_bfloat16* aL = aH + 128 * ALD;
  __nv_bfloat16* bH = aL + 128 * ALD;
  __nv_bfloat16* bL = bH + 64 * ALD;

  const int tid = threadIdx.x;
  const int wid = tid >> 5;
  const int wm = wid >> 1, wn = wid & 1;

  wmma::fragment<wmma::accumulator, 16, 16, 16, float> acc[2][2];
#pragma unroll
  for (int i = 0; i < 2; i++)
#pragma unroll
    for (int j = 0; j < 2; j++) wmma::fill_fragment(acc[i][j], 0.f);

  for (int k0 = 0; k0 < 512; k0 += 32) {
#pragma unroll
    for (int r2 = 0; r2 < 2; r2++) {
      const int idx = tid + r2 * 256;
      const int r = idx >> 2, c8 = (idx & 3) * 8;
      const size_t g = (size_t)(m0 + r) * D_ + k0 + c8;
      *reinterpret_cast<uint4*>(&aH[r * ALD + c8]) = *reinterpret_cast<const uint4*>(&Ah[g]);
      *reinterpret_cast<uint4*>(&aL[r * ALD + c8]) = *reinterpret_cast<const uint4*>(&Al[g]);
    }
    {
      const int r = tid >> 2, c8 = (tid & 3) * 8;
      const size_t g = (size_t)(n0 + r) * D_ + k0 + c8;
      *reinterpret_cast<uint4*>(&bH[r * ALD + c8]) = *reinterpret_cast<const uint4*>(&Bh[g]);
      *reinterpret_cast<uint4*>(&bL[r * ALD + c8]) = *reinterpret_cast<const uint4*>(&Bl[g]);
    }
    __syncthreads();
#pragma unroll
    for (int kk = 0; kk < 32; kk += 16) {
      wmma::fragment<wmma::matrix_a, 16, 16, 16, __nv_bfloat16, wmma::row_major> fah[2], fal[2];
      wmma::fragment<wmma::matrix_b, 16, 16, 16, __nv_bfloat16, wmma::col_major> fbh[2], fbl[2];
#pragma unroll
      for (int i = 0; i < 2; i++) {
        wmma::load_matrix_sync(fah[i], &aH[(wm * 32 + i * 16) * ALD + kk], ALD);
        wmma::load_matrix_sync(fal[i], &aL[(wm * 32 + i * 16) * ALD + kk], ALD);
        wmma::load_matrix_sync(fbh[i], &bH[(wn * 32 + i * 16) * ALD + kk], ALD);
        wmma::load_matrix_sync(fbl[i], &bL[(wn * 32 + i * 16) * ALD + kk], ALD);
      }
#pragma unroll
      for (int i = 0; i < 2; i++)
#pragma unroll
        for (int j = 0; j < 2; j++) {
          wmma::mma_sync(acc[i][j], fah[i], fbh[j], acc[i][j]);
          wmma::mma_sync(acc[i][j], fah[i], fbl[j], acc[i][j]);
          wmma::mma_sync(acc[i][j], fal[i], fbh[j], acc[i][j]);
        }
    }
    __syncthreads();
  }

  float* Cs = reinterpret_cast<float*>(smraw);
#pragma unroll
  for (int i = 0; i < 2; i++)
#pragma unroll
    for (int j = 0; j < 2; j++)
      wmma::store_matrix_sync(&Cs[(wm * 32 + i * 16) * 64 + wn * 32 + j * 16],
                              acc[i][j], 64, wmma::mem_row_major);
  __syncthreads();
#pragma unroll
  for (int r2 = 0; r2 < 8; r2++) {
    const int idx = tid + r2 * 256;
    const int row = idx >> 4, c4 = (idx & 15) * 4;
    float4 o = *reinterpret_cast<const float4*>(&Cs[row * 64 + c4]);
    if (bias) {
      float4 bb = *reinterpret_cast<const float4*>(&bias[n0 + c4]);
      o.x += bb.x; o.y += bb.y; o.z += bb.z; o.w += bb.w;
    }
    const size_t g = (size_t)(m0 + row) * D_ + n0 + c4;
    if (mode == 0) {
      *reinterpret_cast<float4*>(&g_qh[g]) = o;
      float4 vb4 = *reinterpret_cast<const float4*>(&vb[n0 + c4]);
      float4 aq = make_float4(o.x + vb4.x, o.y + vb4.y, o.z + vb4.z, o.w + vb4.w);
      split_store4(aq, g_aqh, g_aql, g);
    } else if (mode == 1) {
      *reinterpret_cast<float4*>(&g_kh[g]) = o;
    } else if (mode == 2) {
      split_store4(o, g_vhh, g_vhl, g);
    } else if (mode == 3) {
      split_store4(o, g_phh, g_phl, g);
    } else {
      *reinterpret_cast<float4*>(&C[g]) = o;
    }
  }
}

__global__ __launch_bounds__(256) void wmma_proj_kernel(
    const float* __restrict__ bq, const float* __restrict__ vb) {
  const int z = blockIdx.z;
  const __nv_bfloat16* Ah = g_inh + (size_t)z * BT_ * D_;
  const __nv_bfloat16* Al = g_inl + (size_t)z * BT_ * D_;
  const int ws = (z < 3) ? 0 : 1;
  wmma_gemm_body(Ah, Al, g_wth + (size_t)ws * D_ * D_, g_wtl + (size_t)ws * D_ * D_,
                 (z < 3) ? bq : nullptr, nullptr, blockIdx.y * 128, blockIdx.x * 64,
                 z, vb);
}

__global__ __launch_bounds__(256) void wmma_final_kernel(const float* __restrict__ bf,
                                                         float* __restrict__ out) {
  wmma_gemm_body(g_ctxh, g_ctxl, g_wth + (size_t)2 * D_ * D_, g_wtl + (size_t)2 * D_ * D_,
                 bf, out, blockIdx.y * 128, blockIdx.x * 64, 4, nullptr);
}

// =====================================================================
// wmma pscore v2 (validated round 13): 128(t) x 64(j), fp16 output.
// =====================================================================
__global__ __launch_bounds__(256) void wmma_pscore_kernel() {
  __shared__ __align__(16) char psm[32768];
  __nv_bfloat16* aH = reinterpret_cast<__nv_bfloat16*>(psm);
  __nv_bfloat16* aL = aH + 128 * ALD;
  __nv_bfloat16* bH = aL + 128 * ALD;
  __nv_bfloat16* bL = bH + 64 * ALD;

  const int tid = threadIdx.x;
  const int wid = tid >> 5;
  const int wm = wid >> 1, wn = wid & 1;
  const int bz = blockIdx.z, b = bz >> 4, h = bz & 15;
  const int t0 = blockIdx.y * 128, j0 = blockIdx.x * 64;

#pragma unroll
  for (int r2 = 0; r2 < 2; r2++) {
    const int idx = tid + r2 * 256;
    const int r = idx >> 2, c8 = (idx & 3) * 8;
    const size_t ga = (size_t)(b * T_ + t0 + r) * D_ + h * DH_ + c8;
    *reinterpret_cast<uint4*>(&aH[r * ALD + c8]) = *reinterpret_cast<const uint4*>(&g_aqh[ga]);
    *reinterpret_cast<uint4*>(&aL[r * ALD + c8]) = *reinterpret_cast<const uint4*>(&g_aql[ga]);
  }
  {
    const int r = tid >> 2, c8 = (tid & 3) * 8;
    const size_t gb = (size_t)(b * T_ + j0 + r) * D_ + h * DH_ + c8;
    *reinterpret_cast<uint4*>(&bH[r * ALD + c8]) = *reinterpret_cast<const uint4*>(&g_phh[gb]);
    *reinterpret_cast<uint4*>(&bL[r * ALD + c8]) = *reinterpret_cast<const uint4*>(&g_phl[gb]);
  }
  __syncthreads();

  wmma::fragment<wmma::accumulator, 16, 16, 16, float> acc[2][2];
#pragma unroll
  for (int i = 0; i < 2; i++)
#pragma unroll
    for (int j = 0; j < 2; j++) wmma::fill_fragment(acc[i][j], 0.f);

#pragma unroll
  for (int kk = 0; kk < 32; kk += 16) {
    wmma::fragment<wmma::matrix_a, 16, 16, 16, __nv_bfloat16, wmma::row_major> fah[2], fal[2];
    wmma::fragment<wmma::matrix_b, 16, 16, 16, __nv_bfloat16, wmma::col_major> fbh[2], fbl[2];
#pragma unroll
    for (int i = 0; i < 2; i++) {
      wmma::load_matrix_sync(fah[i], &aH[(wm * 32 + i * 16) * ALD + kk], ALD);
      wmma::load_matrix_sync(fal[i], &aL[(wm * 32 + i * 16) * ALD + kk], ALD);
      wmma::load_matrix_sync(fbh[i], &bH[(wn * 32 + i * 16) * ALD + kk], ALD);
      wmma::load_matrix_sync(fbl[i], &bL[(wn * 32 + i * 16) * ALD + kk], ALD);
    }
#pragma unroll
    for (int i = 0; i < 2; i++)
#pragma unroll
      for (int j = 0; j < 2; j++) {
        wmma::mma_sync(acc[i][j], fah[i], fbh[j], acc[i][j]);
        wmma::mma_sync(acc[i][j], fah[i], fbl[j], acc[i][j]);
        wmma::mma_sync(acc[i][j], fal[i], fbh[j], acc[i][j]);
      }
  }

  __syncthreads();
  float* Cs = reinterpret_cast<float*>(psm);
#pragma unroll
  for (int i = 0; i < 2; i++)
#pragma unroll
    for (int j = 0; j < 2; j++)
      wmma::store_matrix_sync(&Cs[(wm * 32 + i * 16) * 64 + wn * 32 + j * 16],
                              acc[i][j], 64, wmma::mem_row_major);
  __syncthreads();
#pragma unroll
  for (int it = 0; it < 4; it++) {
    const int e = tid + it * 256;
    const int rs = e >> 3;
    const int c8 = (e & 7) * 8;
    const float* src = &Cs[rs * 64 + c8];
    __half h8[8];
#pragma unroll
    for (int x = 0; x < 8; x++) h8[x] = __float2half(src[x]);
    *reinterpret_cast<uint4*>(
        &g_P[((size_t)bz * T_ + t0 + rs) * T_ + j0 + c8]) =
        *reinterpret_cast<const uint4*>(h8);
  }
}

// =====================================================================
// Hybrid flash v4: scalar f32x2 QK + shift(P fp16) + no-max exp epilogue
// (validated r13), but AV via wmma with persistent fragments and split-bf16
// probs/V (3-product; finalize structure correctness-validated in r7).
// =====================================================================
#define VLD 40
#define PLD2 72
#define CLD 32

__global__ __launch_bounds__(256) void flash_kernel(const float* __restrict__ ubias) {
  __shared__ float Qs[32 * 68];                     // 8704 B (also reused as Cs)
  __shared__ float Ks[32 * 68];
  __shared__ __nv_bfloat16 VsH[64 * VLD];           // 5120 B
  __shared__ __nv_bfloat16 VsL[64 * VLD];
  __shared__ __nv_bfloat16 PsH[64 * PLD2];          // 9216 B
  __shared__ __nv_bfloat16 PsL[64 * PLD2];
  __shared__ float rowX[64];

  const int tid = threadIdx.x;
  const int wid = tid >> 5, lane = tid & 31;
  const int wm = wid >> 1, wn = wid & 1;            // AV warp grid 4m x 2n
  const int bz = blockIdx.y, b = bz >> 4, h = bz & 15;
  const int t0 = blockIdx.x * 64;
  const float isd = 0.04419417382415922f;           // 1/sqrt(512)

  // load Q (+u_bias) transposed, resident (fp32, scalar QK)
#pragma unroll
  for (int r = 0; r < 2; r++) {
    int idx = tid + r * 256;
    int t = idx >> 3, kq = (idx & 7) * 4;
    float4 q4 = *reinterpret_cast<const float4*>(
        &g_qh[(size_t)(b * T_ + t0 + t) * D_ + h * DH_ + kq]);
    float4 u4 = *reinterpret_cast<const float4*>(&ubias[h * DH_ + kq]);
    Qs[(kq + 0) * 68 + t] = q4.x + u4.x;
    Qs[(kq + 1) * 68 + t] = q4.y + u4.y;
    Qs[(kq + 2) * 68 + t] = q4.z + u4.z;
    Qs[(kq + 3) * 68 + t] = q4.w + u4.w;
  }

  const int tx = tid & 15, ty = tid >> 4;
  float lsum[4] = {0.f, 0.f, 0.f, 0.f};

  wmma::fragment<wmma::accumulator, 16, 16, 16, float> accO;
  wmma::fill_fragment(accO, 0.f);

  for (int c = 0; c < 16; c++) {
    const int s0 = c * 64;
    // load K chunk transposed (fp32) + V chunk (bf16 hi/lo)
#pragma unroll
    for (int r = 0; r < 2; r++) {
      int idx = tid + r * 256;
      int s = idx >> 3, kq = (idx & 7) * 4;
      float4 k4 = *reinterpret_cast<const float4*>(
          &g_kh[(size_t)(b * T_ + s0 + s) * D_ + h * DH_ + kq]);
      Ks[(kq + 0) * 68 + s] = k4.x; Ks[(kq + 1) * 68 + s] = k4.y;
      Ks[(kq + 2) * 68 + s] = k4.z; Ks[(kq + 3) * 68 + s] = k4.w;
    }
    {
      const int vr = tid >> 2, vc8 = (tid & 3) * 8;
      const size_t g = (size_t)(b * T_ + s0 + vr) * D_ + h * DH_ + vc8;
      *reinterpret_cast<uint4*>(&VsH[vr * VLD + vc8]) =
          *reinterpret_cast<const uint4*>(&g_vhh[g]);
      *reinterpret_cast<uint4*>(&VsL[vr * VLD + vc8]) =
          *reinterpret_cast<const uint4*>(&g_vhl[g]);
    }
    __syncthreads();

    // ---- scalar QK (f32x2), 4t x 4s per thread ----
    u64 acc[4][2];
#pragma unroll
    for (int i = 0; i < 4; i++) { acc[i][0] = 0ull; acc[i][1] = 0ull; }
#pragma unroll
    for (int kk = 0; kk < 32; kk++) {
      float4 a4 = *reinterpret_cast<const float4*>(&Qs[kk * 68 + ty * 4]);
      ulonglong2 b2 = *reinterpret_cast<const ulonglong2*>(&Ks[kk * 68 + tx * 4]);
      u64 a0 = pack2(a4.x, a4.x), a1 = pack2(a4.y, a4.y);
      u64 a2 = pack2(a4.z, a4.z), a3 = pack2(a4.w, a4.w);
      fma2(acc[0][0], a0, b2.x); fma2(acc[0][1], a0, b2.y);
      fma2(acc[1][0], a1, b2.x); fma2(acc[1][1], a1, b2.y);
      fma2(acc[2][0], a2, b2.x); fma2(acc[2][1], a2, b2.y);
      fma2(acc[3][0], a3, b2.x); fma2(acc[3][1], a3, b2.y);
    }

    // ---- epilogue: +shiftP (fp16, coalesced j=s+const), exp, split probs ----
#pragma unroll
    for (int i = 0; i < 4; i++) {
      const int trow = ty * 4 + i;
      const int t = t0 + trow;
      const size_t rowb = ((size_t)bz * T_ + t) * T_;
      float2 lo = unpack2(acc[i][0]), hi = unpack2(acc[i][1]);
      float v[4] = {lo.x, lo.y, hi.x, hi.y};
#pragma unroll
      for (int j = 0; j < 4; j++) {
        const int s = s0 + tx * 4 + j;
        float pv;
        if (s <= t)          pv = __half2float(g_P[rowb + (s - t + (T_ - 1))]);
        else if (s == t + 1) pv = 0.f;
        else                 pv = __half2float(g_P[rowb + T_ + (s - t - 2)]);
        v[j] = __expf((v[j] + pv) * isd);
      }
      lsum[i] += (v[0] + v[1]) + (v[2] + v[3]);
      __nv_bfloat162 h01, h23, l01, l23;
      split_bf16(v[0], h01.x, l01.x); split_bf16(v[1], h01.y, l01.y);
      split_bf16(v[2], h23.x, l23.x); split_bf16(v[3], h23.y, l23.y);
      *reinterpret_cast<__nv_bfloat162*>(&PsH[trow * PLD2 + tx * 4]) = h01;
      *reinterpret_cast<__nv_bfloat162*>(&PsH[trow * PLD2 + tx * 4 + 2]) = h23;
      *reinterpret_cast<__nv_bfloat162*>(&PsL[trow * PLD2 + tx * 4]) = l01;
      *reinterpret_cast<__nv_bfloat162*>(&PsL[trow * PLD2 + tx * 4 + 2]) = l23;
    }
    __syncthreads();

    // ---- AV via wmma: warp (wm,wn) owns out rows wm*16.., cols wn*16.. ----
#pragma unroll
    for (int kk = 0; kk < 64; kk += 16) {
      wmma::fragment<wmma::matrix_a, 16, 16, 16, __nv_bfloat16, wmma::row_major> pah, pal;
      wmma::fragment<wmma::matrix_b, 16, 16, 16, __nv_bfloat16, wmma::row_major> fvh, fvl;
      wmma::load_matrix_sync(pah, &PsH[(wm * 16) * PLD2 + kk], PLD2);
      wmma::load_matrix_sync(pal, &PsL[(wm * 16) * PLD2 + kk], PLD2);
      wmma::load_matrix_sync(fvh, &VsH[kk * VLD + wn * 16], VLD);
      wmma::load_matrix_sync(fvl, &VsL[kk * VLD + wn * 16], VLD);
      wmma::mma_sync(accO, pah, fvh, accO);
      wmma::mma_sync(accO, pah, fvl, accO);
      wmma::mma_sync(accO, pal, fvh, accO);
    }
    __syncthreads();
  }

  // ---- finalize: reduce row sums, normalize, store ctx splits ----
#pragma unroll
  for (int i = 0; i < 4; i++) {
    float l = lsum[i];
    l += __shfl_xor_sync(0xffffffffu, l, 1);
    l += __shfl_xor_sync(0xffffffffu, l, 2);
    l += __shfl_xor_sync(0xffffffffu, l, 4);
    l += __shfl_xor_sync(0xffffffffu, l, 8);
    if (tx == 0) rowX[ty * 4 + i] = 1.0f / l;
  }
  float* Cs = Qs;  // 64 x 32 fp32 = 8192 B <= sizeof(Qs)
  wmma::store_matrix_sync(&Cs[(wm * 16) * CLD + wn * 16], accO, CLD,
                          wmma::mem_row_major);
  __syncthreads();
  {
    const int row = tid >> 2, c8 = (tid & 3) * 8;
    const float inv = rowX[row];
    float4 a = *reinterpret_cast<const float4*>(&Cs[row * CLD + c8]);
    float4 bb = *reinterpret_cast<const float4*>(&Cs[row * CLD + c8 + 4]);
    a.x *= inv; a.y *= inv; a.z *= inv; a.w *= inv;
    bb.x *= inv; bb.y *= inv; bb.z *= inv; bb.w *= inv;
    const size_t base = (size_t)(b * T_ + t0 + row) * D_ + h * DH_ + c8;
    split_store4(a, g_ctxh, g_ctxl, base);
    split_store4(bb, g_ctxh, g_ctxl, base + 4);
  }
}

// =====================================================================
extern "C" void kernel_launch(void* const* d_in, const int* in_sizes, int n_in,
                              void* d_out, int out_size) {
  const float* q   = (const float*)d_in[0];
  const float* k   = (const float*)d_in[1];
  const float* v   = (const float*)d_in[2];
  const float* pos = (const float*)d_in[3];
  const float* Wq  = (const float*)d_in[4];
  const float* bq  = (const float*)d_in[5];
  const float* Wp  = (const float*)d_in[6];
  const float* Wf  = (const float*)d_in[7];
  const float* bf  = (const float*)d_in[8];
  const float* ub  = (const float*)d_in[9];
  const float* vb  = (const float*)d_in[10];
  float* out = (float*)d_out;

  convert_inputs_kernel<<<dim3(BT_ * D_ / 1024, 4), 256>>>(q, k, v, pos);
  convert_w_kernel<<<dim3(16, 16, 3), 256>>>(Wq, Wp, Wf);

  wmma_proj_kernel<<<dim3(8, 32, 4), 256>>>(bq, vb);

  wmma_pscore_kernel<<<dim3(16, 8, 64), 256>>>();

  flash_kernel<<<dim3(16, 64), 256>>>(ub);

  wmma_final_kernel<<<dim3(8, 32), 256>>>(bf, out);
}

// round 15
// speedup vs baseline: 1.4466x; 1.0109x over previous
#include <cuda_runtime.h>
#include <cuda_bf16.h>
#include <cuda_fp16.h>
#include <mma.h>
#include <cstddef>
#include <cstdint>

using namespace nvcuda;

#define B_ 4
#define T_ 1024
#define D_ 512
#define H_ 16
#define DH_ 32
#define BT_ (B_ * T_)

// ---- scratch (static device globals; no runtime allocation) ----
__device__ __half g_P[(size_t)B_ * H_ * T_ * T_];  // 128 MB, unshifted pos scores

__device__ __nv_bfloat16 g_inh[4 * BT_ * D_];   // hi(q,k,v,pos)
__device__ __nv_bfloat16 g_inl[4 * BT_ * D_];   // lo
__device__ __nv_bfloat16 g_wth[3 * D_ * D_];    // hi(Wq^T, Wp^T, Wf^T)  [n][k]
__device__ __nv_bfloat16 g_wtl[3 * D_ * D_];
__device__ __nv_bfloat16 g_ctxh[BT_ * D_];
__device__ __nv_bfloat16 g_ctxl[BT_ * D_];
__device__ __nv_bfloat16 g_cqh[BT_ * D_];       // hi(qh + u_bias)
__device__ __nv_bfloat16 g_cql[BT_ * D_];
__device__ __nv_bfloat16 g_aqh[BT_ * D_];       // hi(qh + v_bias)
__device__ __nv_bfloat16 g_aql[BT_ * D_];
__device__ __nv_bfloat16 g_khh[BT_ * D_];       // hi(kh)
__device__ __nv_bfloat16 g_khl[BT_ * D_];
__device__ __nv_bfloat16 g_phh[BT_ * D_];       // hi(ph)
__device__ __nv_bfloat16 g_phl[BT_ * D_];
__device__ __nv_bfloat16 g_vhh[BT_ * D_];       // hi(vh)
__device__ __nv_bfloat16 g_vhl[BT_ * D_];

// =====================================================================
// fp32 -> bf16 hi/lo split
// =====================================================================
__device__ __forceinline__ void split_bf16(float x, __nv_bfloat16& h, __nv_bfloat16& l) {
  h = __float2bfloat16(x);
  l = __float2bfloat16(x - __bfloat162float(h));
}

__device__ __forceinline__ void split_store4(float4 x, __nv_bfloat16* Hh,
                                             __nv_bfloat16* Ll, size_t i) {
  __nv_bfloat162 h0, h1, l0, l1;
  split_bf16(x.x, h0.x, l0.x); split_bf16(x.y, h0.y, l0.y);
  split_bf16(x.z, h1.x, l1.x); split_bf16(x.w, h1.y, l1.y);
  *reinterpret_cast<__nv_bfloat162*>(&Hh[i]) = h0;
  *reinterpret_cast<__nv_bfloat162*>(&Hh[i + 2]) = h1;
  *reinterpret_cast<__nv_bfloat162*>(&Ll[i]) = l0;
  *reinterpret_cast<__nv_bfloat162*>(&Ll[i + 2]) = l1;
}

__global__ __launch_bounds__(256) void convert_inputs_kernel(
    const float* __restrict__ q, const float* __restrict__ k,
    const float* __restrict__ v, const float* __restrict__ pos) {
  const int z = blockIdx.y;
  const float* src = (z == 0) ? q : (z == 1) ? k : (z == 2) ? v : pos;
  const size_t i = ((size_t)blockIdx.x * 256 + threadIdx.x) * 4;
  split_store4(*reinterpret_cast<const float4*>(&src[i]),
               g_inh + (size_t)z * BT_ * D_, g_inl + (size_t)z * BT_ * D_, i);
}

// W [k][n] -> Wt [n][k] hi/lo bf16 (32x32 smem tile transpose)
__global__ __launch_bounds__(256) void convert_w_kernel(
    const float* __restrict__ Wq, const float* __restrict__ Wp,
    const float* __restrict__ Wf) {
  const int z = blockIdx.z;
  const float* W = (z == 0) ? Wq : (z == 1) ? Wp : Wf;
  __nv_bfloat16* Hh = g_wth + (size_t)z * D_ * D_;
  __nv_bfloat16* Ll = g_wtl + (size_t)z * D_ * D_;
  __shared__ float tile[32][33];
  const int tx = threadIdx.x & 31, ty = threadIdx.x >> 5;
  const int k0 = blockIdx.y * 32, n0 = blockIdx.x * 32;
#pragma unroll
  for (int r = 0; r < 4; r++)
    tile[ty + 8 * r][tx] = W[(size_t)(k0 + ty + 8 * r) * D_ + n0 + tx];
  __syncthreads();
#pragma unroll
  for (int r = 0; r < 4; r++) {
    const int n = n0 + ty + 8 * r;
    float x = tile[tx][ty + 8 * r];
    __nv_bfloat16 h, l; split_bf16(x, h, l);
    Hh[(size_t)n * D_ + k0 + tx] = h;
    Ll[(size_t)n * D_ + k0 + tx] = l;
  }
}

// =====================================================================
// wmma split-bf16 GEMM (validated round 6) with fused split epilogues.
// mode: 0=q (cq & aq splits), 1=kh splits, 2=vh splits,
//       3=ph splits, 4=final (fp32 out + bias)
// =====================================================================
#define ALD 40

__device__ __forceinline__ void wmma_gemm_body(
    const __nv_bfloat16* __restrict__ Ah, const __nv_bfloat16* __restrict__ Al,
    const __nv_bfloat16* __restrict__ Bh, const __nv_bfloat16* __restrict__ Bl,
    const float* __restrict__ bias, float* __restrict__ C, int m0, int n0,
    int mode, const float* __restrict__ ub, const float* __restrict__ vb) {
  __shared__ __align__(16) char smraw[32768];
  __nv_bfloat16* aH = reinterpret_cast<__nv_bfloat16*>(smraw);
  __nv_bfloat16* aL = aH + 128 * ALD;
  __nv_bfloat16* bH = aL + 128 * ALD;
  __nv_bfloat16* bL = bH + 64 * ALD;

  const int tid = threadIdx.x;
  const int wid = tid >> 5;
  const int wm = wid >> 1, wn = wid & 1;

  wmma::fragment<wmma::accumulator, 16, 16, 16, float> acc[2][2];
#pragma unroll
  for (int i = 0; i < 2; i++)
#pragma unroll
    for (int j = 0; j < 2; j++) wmma::fill_fragment(acc[i][j], 0.f);

  for (int k0 = 0; k0 < 512; k0 += 32) {
#pragma unroll
    for (int r2 = 0; r2 < 2; r2++) {
      const int idx = tid + r2 * 256;
      const int r = idx >> 2, c8 = (idx & 3) * 8;
      const size_t g = (size_t)(m0 + r) * D_ + k0 + c8;
      *reinterpret_cast<uint4*>(&aH[r * ALD + c8]) = *reinterpret_cast<const uint4*>(&Ah[g]);
      *reinterpret_cast<uint4*>(&aL[r * ALD + c8]) = *reinterpret_cast<const uint4*>(&Al[g]);
    }
    {
      const int r = tid >> 2, c8 = (tid & 3) * 8;
      const size_t g = (size_t)(n0 + r) * D_ + k0 + c8;
      *reinterpret_cast<uint4*>(&bH[r * ALD + c8]) = *reinterpret_cast<const uint4*>(&Bh[g]);
      *reinterpret_cast<uint4*>(&bL[r * ALD + c8]) = *reinterpret_cast<const uint4*>(&Bl[g]);
    }
    __syncthreads();
#pragma unroll
    for (int kk = 0; kk < 32; kk += 16) {
      wmma::fragment<wmma::matrix_a, 16, 16, 16, __nv_bfloat16, wmma::row_major> fah[2], fal[2];
      wmma::fragment<wmma::matrix_b, 16, 16, 16, __nv_bfloat16, wmma::col_major> fbh[2], fbl[2];
#pragma unroll
      for (int i = 0; i < 2; i++) {
        wmma::load_matrix_sync(fah[i], &aH[(wm * 32 + i * 16) * ALD + kk], ALD);
        wmma::load_matrix_sync(fal[i], &aL[(wm * 32 + i * 16) * ALD + kk], ALD);
        wmma::load_matrix_sync(fbh[i], &bH[(wn * 32 + i * 16) * ALD + kk], ALD);
        wmma::load_matrix_sync(fbl[i], &bL[(wn * 32 + i * 16) * ALD + kk], ALD);
      }
#pragma unroll
      for (int i = 0; i < 2; i++)
#pragma unroll
        for (int j = 0; j < 2; j++) {
          wmma::mma_sync(acc[i][j], fah[i], fbh[j], acc[i][j]);
          wmma::mma_sync(acc[i][j], fah[i], fbl[j], acc[i][j]);
          wmma::mma_sync(acc[i][j], fal[i], fbh[j], acc[i][j]);
        }
    }
    __syncthreads();
  }

  float* Cs = reinterpret_cast<float*>(smraw);
#pragma unroll
  for (int i = 0; i < 2; i++)
#pragma unroll
    for (int j = 0; j < 2; j++)
      wmma::store_matrix_sync(&Cs[(wm * 32 + i * 16) * 64 + wn * 32 + j * 16],
                              acc[i][j], 64, wmma::mem_row_major);
  __syncthreads();
#pragma unroll
  for (int r2 = 0; r2 < 8; r2++) {
    const int idx = tid + r2 * 256;
    const int row = idx >> 4, c4 = (idx & 15) * 4;
    float4 o = *reinterpret_cast<const float4*>(&Cs[row * 64 + c4]);
    if (bias) {
      float4 bb = *reinterpret_cast<const float4*>(&bias[n0 + c4]);
      o.x += bb.x; o.y += bb.y; o.z += bb.z; o.w += bb.w;
    }
    const size_t g = (size_t)(m0 + row) * D_ + n0 + c4;
    if (mode == 0) {
      float4 ub4 = *reinterpret_cast<const float4*>(&ub[n0 + c4]);
      float4 vb4 = *reinterpret_cast<const float4*>(&vb[n0 + c4]);
      float4 cq = make_float4(o.x + ub4.x, o.y + ub4.y, o.z + ub4.z, o.w + ub4.w);
      float4 aq = make_float4(o.x + vb4.x, o.y + vb4.y, o.z + vb4.z, o.w + vb4.w);
      split_store4(cq, g_cqh, g_cql, g);
      split_store4(aq, g_aqh, g_aql, g);
    } else if (mode == 1) {
      split_store4(o, g_khh, g_khl, g);
    } else if (mode == 2) {
      split_store4(o, g_vhh, g_vhl, g);
    } else if (mode == 3) {
      split_store4(o, g_phh, g_phl, g);
    } else {
      *reinterpret_cast<float4*>(&C[g]) = o;
    }
  }
}

__global__ __launch_bounds__(256) void wmma_proj_kernel(
    const float* __restrict__ bq, const float* __restrict__ ub,
    const float* __restrict__ vb) {
  const int z = blockIdx.z;
  const __nv_bfloat16* Ah = g_inh + (size_t)z * BT_ * D_;
  const __nv_bfloat16* Al = g_inl + (size_t)z * BT_ * D_;
  const int ws = (z < 3) ? 0 : 1;
  wmma_gemm_body(Ah, Al, g_wth + (size_t)ws * D_ * D_, g_wtl + (size_t)ws * D_ * D_,
                 (z < 3) ? bq : nullptr, nullptr, blockIdx.y * 128, blockIdx.x * 64,
                 z, ub, vb);
}

__global__ __launch_bounds__(256) void wmma_final_kernel(const float* __restrict__ bf,
                                                         float* __restrict__ out) {
  wmma_gemm_body(g_ctxh, g_ctxl, g_wth + (size_t)2 * D_ * D_, g_wtl + (size_t)2 * D_ * D_,
                 bf, out, blockIdx.y * 128, blockIdx.x * 64, 4, nullptr, nullptr);
}

// =====================================================================
// wmma pscore v2 (validated round 13): 128(t) x 64(j), fp16 output.
// =====================================================================
__global__ __launch_bounds__(256) void wmma_pscore_kernel() {
  __shared__ __align__(16) char psm[32768];
  __nv_bfloat16* aH = reinterpret_cast<__nv_bfloat16*>(psm);
  __nv_bfloat16* aL = aH + 128 * ALD;
  __nv_bfloat16* bH = aL + 128 * ALD;
  __nv_bfloat16* bL = bH + 64 * ALD;

  const int tid = threadIdx.x;
  const int wid = tid >> 5;
  const int wm = wid >> 1, wn = wid & 1;
  const int bz = blockIdx.z, b = bz >> 4, h = bz & 15;
  const int t0 = blockIdx.y * 128, j0 = blockIdx.x * 64;

#pragma unroll
  for (int r2 = 0; r2 < 2; r2++) {
    const int idx = tid + r2 * 256;
    const int r = idx >> 2, c8 = (idx & 3) * 8;
    const size_t ga = (size_t)(b * T_ + t0 + r) * D_ + h * DH_ + c8;
    *reinterpret_cast<uint4*>(&aH[r * ALD + c8]) = *reinterpret_cast<const uint4*>(&g_aqh[ga]);
    *reinterpret_cast<uint4*>(&aL[r * ALD + c8]) = *reinterpret_cast<const uint4*>(&g_aql[ga]);
  }
  {
    const int r = tid >> 2, c8 = (tid & 3) * 8;
    const size_t gb = (size_t)(b * T_ + j0 + r) * D_ + h * DH_ + c8;
    *reinterpret_cast<uint4*>(&bH[r * ALD + c8]) = *reinterpret_cast<const uint4*>(&g_phh[gb]);
    *reinterpret_cast<uint4*>(&bL[r * ALD + c8]) = *reinterpret_cast<const uint4*>(&g_phl[gb]);
  }
  __syncthreads();

  wmma::fragment<wmma::accumulator, 16, 16, 16, float> acc[2][2];
#pragma unroll
  for (int i = 0; i < 2; i++)
#pragma unroll
    for (int j = 0; j < 2; j++) wmma::fill_fragment(acc[i][j], 0.f);

#pragma unroll
  for (int kk = 0; kk < 32; kk += 16) {
    wmma::fragment<wmma::matrix_a, 16, 16, 16, __nv_bfloat16, wmma::row_major> fah[2], fal[2];
    wmma::fragment<wmma::matrix_b, 16, 16, 16, __nv_bfloat16, wmma::col_major> fbh[2], fbl[2];
#pragma unroll
    for (int i = 0; i < 2; i++) {
      wmma::load_matrix_sync(fah[i], &aH[(wm * 32 + i * 16) * ALD + kk], ALD);
      wmma::load_matrix_sync(fal[i], &aL[(wm * 32 + i * 16) * ALD + kk], ALD);
      wmma::load_matrix_sync(fbh[i], &bH[(wn * 32 + i * 16) * ALD + kk], ALD);
      wmma::load_matrix_sync(fbl[i], &bL[(wn * 32 + i * 16) * ALD + kk], ALD);
    }
#pragma unroll
    for (int i = 0; i < 2; i++)
#pragma unroll
      for (int j = 0; j < 2; j++) {
        wmma::mma_sync(acc[i][j], fah[i], fbh[j], acc[i][j]);
        wmma::mma_sync(acc[i][j], fah[i], fbl[j], acc[i][j]);
        wmma::mma_sync(acc[i][j], fal[i], fbh[j], acc[i][j]);
      }
  }

  __syncthreads();
  float* Cs = reinterpret_cast<float*>(psm);
#pragma unroll
  for (int i = 0; i < 2; i++)
#pragma unroll
    for (int j = 0; j < 2; j++)
      wmma::store_matrix_sync(&Cs[(wm * 32 + i * 16) * 64 + wn * 32 + j * 16],
                              acc[i][j], 64, wmma::mem_row_major);
  __syncthreads();
#pragma unroll
  for (int it = 0; it < 4; it++) {
    const int e = tid + it * 256;
    const int rs = e >> 3;
    const int c8 = (e & 7) * 8;
    const float* src = &Cs[rs * 64 + c8];
    __half h8[8];
#pragma unroll
    for (int x = 0; x < 8; x++) h8[x] = __float2half(src[x]);
    *reinterpret_cast<uint4*>(
        &g_P[((size_t)bz * T_ + t0 + rs) * T_ + j0 + c8]) =
        *reinterpret_cast<const uint4*>(h8);
  }
}

// =====================================================================
// Flash v5: fully tensorized. wmma QK (split-bf16) + shift(P fp16) +
// no-max exp epilogue (coalesced, r13) + wmma AV (persistent frags, r14).
// Block = 64 q rows x one (b,h); 16 chunks of 64 keys; 256 threads.
// Dynamic smem ~65.3 KB -> 3 CTAs/SM.
// =====================================================================
#define VLD 40
#define SLD 68
#define PLD2 72
#define CLD 32
// byte offsets in dynamic smem
#define OQH 0
#define OQL (OQH + 64 * VLD * 2)
#define OKH (OQL + 64 * VLD * 2)
#define OKL (OKH + 64 * VLD * 2)
#define OVH (OKL + 64 * VLD * 2)
#define OVL (OVH + 64 * VLD * 2)
#define OSS (OVL + 64 * VLD * 2)
#define OPH (OSS + 64 * SLD * 4)
#define OPL (OPH + 64 * PLD2 * 2)
#define OLR (OPL + 64 * PLD2 * 2)
#define FLASH_SMEM (OLR + 64 * 4)

__global__ __launch_bounds__(256) void flash_kernel() {
  extern __shared__ __align__(16) char sm[];
  __nv_bfloat16* QhS = reinterpret_cast<__nv_bfloat16*>(sm + OQH);
  __nv_bfloat16* QlS = reinterpret_cast<__nv_bfloat16*>(sm + OQL);
  __nv_bfloat16* KhS = reinterpret_cast<__nv_bfloat16*>(sm + OKH);
  __nv_bfloat16* KlS = reinterpret_cast<__nv_bfloat16*>(sm + OKL);
  __nv_bfloat16* VhS = reinterpret_cast<__nv_bfloat16*>(sm + OVH);
  __nv_bfloat16* VlS = reinterpret_cast<__nv_bfloat16*>(sm + OVL);
  float* Ss = reinterpret_cast<float*>(sm + OSS);
  __nv_bfloat16* PsH = reinterpret_cast<__nv_bfloat16*>(sm + OPH);
  __nv_bfloat16* PsL = reinterpret_cast<__nv_bfloat16*>(sm + OPL);
  float* rowX = reinterpret_cast<float*>(sm + OLR);

  const int tid = threadIdx.x;
  const int wid = tid >> 5;
  const int wm = wid >> 1, wn = wid & 1;            // warp grid 4m x 2n
  const int bz = blockIdx.y, b = bz >> 4, h = bz & 15;
  const int t0 = blockIdx.x * 64;
  const float isd = 0.04419417382415922f;           // 1/sqrt(512)

  // load Q splits (64 x 32), resident
  const int pr = tid >> 2, pc8 = (tid & 3) * 8;
  {
    const size_t g = (size_t)(b * T_ + t0 + pr) * D_ + h * DH_ + pc8;
    *reinterpret_cast<uint4*>(&QhS[pr * VLD + pc8]) =
        *reinterpret_cast<const uint4*>(&g_cqh[g]);
    *reinterpret_cast<uint4*>(&QlS[pr * VLD + pc8]) =
        *reinterpret_cast<const uint4*>(&g_cql[g]);
  }

  const int tx = tid & 15, ty = tid >> 4;           // epilogue mapping (r13)
  float lsum[4] = {0.f, 0.f, 0.f, 0.f};

  wmma::fragment<wmma::accumulator, 16, 16, 16, float> accO;
  wmma::fill_fragment(accO, 0.f);

  for (int c = 0; c < 16; c++) {
    const int s0 = c * 64;
    // ---- load K,V split chunks (64 x 32 each) ----
    {
      const size_t g = (size_t)(b * T_ + s0 + pr) * D_ + h * DH_ + pc8;
      *reinterpret_cast<uint4*>(&KhS[pr * VLD + pc8]) =
          *reinterpret_cast<const uint4*>(&g_khh[g]);
      *reinterpret_cast<uint4*>(&KlS[pr * VLD + pc8]) =
          *reinterpret_cast<const uint4*>(&g_khl[g]);
      *reinterpret_cast<uint4*>(&VhS[pr * VLD + pc8]) =
          *reinterpret_cast<const uint4*>(&g_vhh[g]);
      *reinterpret_cast<uint4*>(&VlS[pr * VLD + pc8]) =
          *reinterpret_cast<const uint4*>(&g_vhl[g]);
    }
    __syncthreads();

    // ---- QK via wmma: warp (wm,wn) -> S stripe rows wm*16.., cols wn*32.. ----
    {
      wmma::fragment<wmma::accumulator, 16, 16, 16, float> accS[2];
      wmma::fill_fragment(accS[0], 0.f);
      wmma::fill_fragment(accS[1], 0.f);
#pragma unroll
      for (int kk = 0; kk < 32; kk += 16) {
        wmma::fragment<wmma::matrix_a, 16, 16, 16, __nv_bfloat16, wmma::row_major> fah, fal;
        wmma::load_matrix_sync(fah, &QhS[(wm * 16) * VLD + kk], VLD);
        wmma::load_matrix_sync(fal, &QlS[(wm * 16) * VLD + kk], VLD);
#pragma unroll
        for (int j = 0; j < 2; j++) {
          wmma::fragment<wmma::matrix_b, 16, 16, 16, __nv_bfloat16, wmma::col_major> fbh, fbl;
          wmma::load_matrix_sync(fbh, &KhS[(wn * 32 + j * 16) * VLD + kk], VLD);
          wmma::load_matrix_sync(fbl, &KlS[(wn * 32 + j * 16) * VLD + kk], VLD);
          wmma::mma_sync(accS[j], fah, fbh, accS[j]);
          wmma::mma_sync(accS[j], fah, fbl, accS[j]);
          wmma::mma_sync(accS[j], fal, fbh, accS[j]);
        }
      }
      wmma::store_matrix_sync(&Ss[(wm * 16) * SLD + wn * 32], accS[0], SLD,
                              wmma::mem_row_major);
      wmma::store_matrix_sync(&Ss[(wm * 16) * SLD + wn * 32 + 16], accS[1], SLD,
                              wmma::mem_row_major);
    }
    __syncthreads();

    // ---- epilogue: +shiftP (fp16, coalesced), exp, split probs (r13) ----
#pragma unroll
    for (int i = 0; i < 4; i++) {
      const int trow = ty * 4 + i;
      const int t = t0 + trow;
      const size_t rowb = ((size_t)bz * T_ + t) * T_;
      float v[4];
#pragma unroll
      for (int j = 0; j < 4; j++) {
        const int s = s0 + tx * 4 + j;
        float pv;
        if (s <= t)          pv = __half2float(g_P[rowb + (s - t + (T_ - 1))]);
        else if (s == t + 1) pv = 0.f;
        else                 pv = __half2float(g_P[rowb + T_ + (s - t - 2)]);
        v[j] = __expf((Ss[trow * SLD + tx * 4 + j] + pv) * isd);
      }
      lsum[i] += (v[0] + v[1]) + (v[2] + v[3]);
      __nv_bfloat162 h01, h23, l01, l23;
      split_bf16(v[0], h01.x, l01.x); split_bf16(v[1], h01.y, l01.y);
      split_bf16(v[2], h23.x, l23.x); split_bf16(v[3], h23.y, l23.y);
      *reinterpret_cast<__nv_bfloat162*>(&PsH[trow * PLD2 + tx * 4]) = h01;
      *reinterpret_cast<__nv_bfloat162*>(&PsH[trow * PLD2 + tx * 4 + 2]) = h23;
      *reinterpret_cast<__nv_bfloat162*>(&PsL[trow * PLD2 + tx * 4]) = l01;
      *reinterpret_cast<__nv_bfloat162*>(&PsL[trow * PLD2 + tx * 4 + 2]) = l23;
    }
    __syncthreads();

    // ---- AV via wmma (r14): warp -> out rows wm*16.., cols wn*16.. ----
#pragma unroll
    for (int kk = 0; kk < 64; kk += 16) {
      wmma::fragment<wmma::matrix_a, 16, 16, 16, __nv_bfloat16, wmma::row_major> pah, pal;
      wmma::fragment<wmma::matrix_b, 16, 16, 16, __nv_bfloat16, wmma::row_major> fvh, fvl;
      wmma::load_matrix_sync(pah, &PsH[(wm * 16) * PLD2 + kk], PLD2);
      wmma::load_matrix_sync(pal, &PsL[(wm * 16) * PLD2 + kk], PLD2);
      wmma::load_matrix_sync(fvh, &VhS[kk * VLD + wn * 16], VLD);
      wmma::load_matrix_sync(fvl, &VlS[kk * VLD + wn * 16], VLD);
      wmma::mma_sync(accO, pah, fvh, accO);
      wmma::mma_sync(accO, pah, fvl, accO);
      wmma::mma_sync(accO, pal, fvh, accO);
    }
    __syncthreads();
  }

  // ---- finalize: reduce row sums, normalize, store ctx splits (r14) ----
#pragma unroll
  for (int i = 0; i < 4; i++) {
    float l = lsum[i];
    l += __shfl_xor_sync(0xffffffffu, l, 1);
    l += __shfl_xor_sync(0xffffffffu, l, 2);
    l += __shfl_xor_sync(0xffffffffu, l, 4);
    l += __shfl_xor_sync(0xffffffffu, l, 8);
    if (tx == 0) rowX[ty * 4 + i] = 1.0f / l;
  }
  float* Cs = Ss;  // 64 x 32 fp32 fits in Ss region
  wmma::store_matrix_sync(&Cs[(wm * 16) * CLD + wn * 16], accO, CLD,
                          wmma::mem_row_major);
  __syncthreads();
  {
    const int row = tid >> 2, c8 = (tid & 3) * 8;
    const float inv = rowX[row];
    float4 a = *reinterpret_cast<const float4*>(&Cs[row * CLD + c8]);
    float4 bb = *reinterpret_cast<const float4*>(&Cs[row * CLD + c8 + 4]);
    a.x *= inv; a.y *= inv; a.z *= inv; a.w *= inv;
    bb.x *= inv; bb.y *= inv; bb.z *= inv; bb.w *= inv;
    const size_t base = (size_t)(b * T_ + t0 + row) * D_ + h * DH_ + c8;
    split_store4(a, g_ctxh, g_ctxl, base);
    split_store4(bb, g_ctxh, g_ctxl, base + 4);
  }
}

// =====================================================================
extern "C" void kernel_launch(void* const* d_in, const int* in_sizes, int n_in,
                              void* d_out, int out_size) {
  const float* q   = (const float*)d_in[0];
  const float* k   = (const float*)d_in[1];
  const float* v   = (const float*)d_in[2];
  const float* pos = (const float*)d_in[3];
  const float* Wq  = (const float*)d_in[4];
  const float* bq  = (const float*)d_in[5];
  const float* Wp  = (const float*)d_in[6];
  const float* Wf  = (const float*)d_in[7];
  const float* bf  = (const float*)d_in[8];
  const float* ub  = (const float*)d_in[9];
  const float* vb  = (const float*)d_in[10];
  float* out = (float*)d_out;

  static bool attr_done = false;
  if (!attr_done) {
    cudaFuncSetAttribute(flash_kernel,
                         cudaFuncAttributeMaxDynamicSharedMemorySize, FLASH_SMEM);
    attr_done = true;
  }

  convert_inputs_kernel<<<dim3(BT_ * D_ / 1024, 4), 256>>>(q, k, v, pos);
  convert_w_kernel<<<dim3(16, 16, 3), 256>>>(Wq, Wp, Wf);

  wmma_proj_kernel<<<dim3(8, 32, 4), 256>>>(bq, ub, vb);

  wmma_pscore_kernel<<<dim3(16, 8, 64), 256>>>();

  flash_kernel<<<dim3(16, 64), 256, FLASH_SMEM>>>();

  wmma_final_kernel<<<dim3(8, 32), 256>>>(bf, out);
}

// round 17
// speedup vs baseline: 1.4616x; 1.0103x over previous
#include <cuda_runtime.h>
#include <cuda_bf16.h>
#include <cuda_fp16.h>
#include <mma.h>
#include <cstddef>
#include <cstdint>

using namespace nvcuda;

#define B_ 4
#define T_ 1024
#define D_ 512
#define H_ 16
#define DH_ 32
#define BT_ (B_ * T_)

// ---- scratch (static device globals; no runtime allocation) ----
__device__ __half g_P[(size_t)B_ * H_ * T_ * T_];  // 128 MB, unshifted pos scores

__device__ __nv_bfloat16 g_inh[4 * BT_ * D_];   // hi(q,k,v,pos)
__device__ __nv_bfloat16 g_inl[4 * BT_ * D_];   // lo
__device__ __nv_bfloat16 g_wth[3 * D_ * D_];    // hi(Wq^T, Wp^T, Wf^T)  [n][k]
__device__ __nv_bfloat16 g_wtl[3 * D_ * D_];
__device__ __nv_bfloat16 g_ctxh[BT_ * D_];
__device__ __nv_bfloat16 g_ctxl[BT_ * D_];
__device__ __nv_bfloat16 g_cqh[BT_ * D_];       // hi(qh + u_bias)
__device__ __nv_bfloat16 g_cql[BT_ * D_];
__device__ __nv_bfloat16 g_aqh[BT_ * D_];       // hi(qh + v_bias)
__device__ __nv_bfloat16 g_aql[BT_ * D_];
__device__ __nv_bfloat16 g_khh[BT_ * D_];       // hi(kh)
__device__ __nv_bfloat16 g_khl[BT_ * D_];
__device__ __nv_bfloat16 g_phh[BT_ * D_];       // hi(ph)
__device__ __nv_bfloat16 g_phl[BT_ * D_];
__device__ __nv_bfloat16 g_vhh[BT_ * D_];       // hi(vh)
__device__ __nv_bfloat16 g_vhl[BT_ * D_];

// =====================================================================
// fp32 -> bf16 hi/lo split
// =====================================================================
__device__ __forceinline__ void split_bf16(float x, __nv_bfloat16& h, __nv_bfloat16& l) {
  h = __float2bfloat16(x);
  l = __float2bfloat16(x - __bfloat162float(h));
}

__device__ __forceinline__ void split_store4(float4 x, __nv_bfloat16* Hh,
                                             __nv_bfloat16* Ll, size_t i) {
  __nv_bfloat162 h0, h1, l0, l1;
  split_bf16(x.x, h0.x, l0.x); split_bf16(x.y, h0.y, l0.y);
  split_bf16(x.z, h1.x, l1.x); split_bf16(x.w, h1.y, l1.y);
  *reinterpret_cast<__nv_bfloat162*>(&Hh[i]) = h0;
  *reinterpret_cast<__nv_bfloat162*>(&Hh[i + 2]) = h1;
  *reinterpret_cast<__nv_bfloat162*>(&Ll[i]) = l0;
  *reinterpret_cast<__nv_bfloat162*>(&Ll[i + 2]) = l1;
}

__global__ __launch_bounds__(256) void convert_inputs_kernel(
    const float* __restrict__ q, const float* __restrict__ k,
    const float* __restrict__ v, const float* __restrict__ pos) {
  const int z = blockIdx.y;
  const float* src = (z == 0) ? q : (z == 1) ? k : (z == 2) ? v : pos;
  const size_t i = ((size_t)blockIdx.x * 256 + threadIdx.x) * 4;
  split_store4(*reinterpret_cast<const float4*>(&src[i]),
               g_inh + (size_t)z * BT_ * D_, g_inl + (size_t)z * BT_ * D_, i);
}

// W [k][n] -> Wt [n][k] hi/lo bf16 (32x32 smem tile transpose)
__global__ __launch_bounds__(256) void convert_w_kernel(
    const float* __restrict__ Wq, const float* __restrict__ Wp,
    const float* __restrict__ Wf) {
  const int z = blockIdx.z;
  const float* W = (z == 0) ? Wq : (z == 1) ? Wp : Wf;
  __nv_bfloat16* Hh = g_wth + (size_t)z * D_ * D_;
  __nv_bfloat16* Ll = g_wtl + (size_t)z * D_ * D_;
  __shared__ float tile[32][33];
  const int tx = threadIdx.x & 31, ty = threadIdx.x >> 5;
  const int k0 = blockIdx.y * 32, n0 = blockIdx.x * 32;
#pragma unroll
  for (int r = 0; r < 4; r++)
    tile[ty + 8 * r][tx] = W[(size_t)(k0 + ty + 8 * r) * D_ + n0 + tx];
  __syncthreads();
#pragma unroll
  for (int r = 0; r < 4; r++) {
    const int n = n0 + ty + 8 * r;
    float x = tile[tx][ty + 8 * r];
    __nv_bfloat16 h, l; split_bf16(x, h, l);
    Hh[(size_t)n * D_ + k0 + tx] = h;
    Ll[(size_t)n * D_ + k0 + tx] = l;
  }
}

// =====================================================================
// wmma split-bf16 GEMM v3: K-chunk 64 (half the syncs of r6 body),
// dynamic smem 54 KB. Fused split epilogues.
// mode: 0=q (cq & aq splits), 1=kh splits, 2=vh splits,
//       3=ph splits, 4=final (fp32 out + bias)
// =====================================================================
#define ALD 40
#define ALD2 72
#define GEMM_SMEM 55296  // 2*(128*72*2) + 2*(64*72*2)

__device__ __forceinline__ void wmma_gemm_body(
    const __nv_bfloat16* __restrict__ Ah, const __nv_bfloat16* __restrict__ Al,
    const __nv_bfloat16* __restrict__ Bh, const __nv_bfloat16* __restrict__ Bl,
    const float* __restrict__ bias, float* __restrict__ C, int m0, int n0,
    int mode, const float* __restrict__ ub, const float* __restrict__ vb) {
  extern __shared__ __align__(16) char gsm[];
  __nv_bfloat16* aH = reinterpret_cast<__nv_bfloat16*>(gsm);
  __nv_bfloat16* aL = aH + 128 * ALD2;
  __nv_bfloat16* bH = aL + 128 * ALD2;
  __nv_bfloat16* bL = bH + 64 * ALD2;

  const int tid = threadIdx.x;
  const int wid = tid >> 5;
  const int wm = wid >> 1, wn = wid & 1;

  wmma::fragment<wmma::accumulator, 16, 16, 16, float> acc[2][2];
#pragma unroll
  for (int i = 0; i < 2; i++)
#pragma unroll
    for (int j = 0; j < 2; j++) wmma::fill_fragment(acc[i][j], 0.f);

  for (int k0 = 0; k0 < 512; k0 += 64) {
    // A: 128 rows x 64 k = 1024 uint4-pairs; 4 per thread (hi & lo)
#pragma unroll
    for (int r2 = 0; r2 < 4; r2++) {
      const int idx = tid + r2 * 256;
      const int r = idx >> 3, c8 = (idx & 7) * 8;
      const size_t g = (size_t)(m0 + r) * D_ + k0 + c8;
      *reinterpret_cast<uint4*>(&aH[r * ALD2 + c8]) = *reinterpret_cast<const uint4*>(&Ah[g]);
      *reinterpret_cast<uint4*>(&aL[r * ALD2 + c8]) = *reinterpret_cast<const uint4*>(&Al[g]);
    }
    // B: 64 rows x 64 k = 512 slots; 2 per thread (hi & lo)
#pragma unroll
    for (int r2 = 0; r2 < 2; r2++) {
      const int idx = tid + r2 * 256;
      const int r = idx >> 3, c8 = (idx & 7) * 8;
      const size_t g = (size_t)(n0 + r) * D_ + k0 + c8;
      *reinterpret_cast<uint4*>(&bH[r * ALD2 + c8]) = *reinterpret_cast<const uint4*>(&Bh[g]);
      *reinterpret_cast<uint4*>(&bL[r * ALD2 + c8]) = *reinterpret_cast<const uint4*>(&Bl[g]);
    }
    __syncthreads();
#pragma unroll
    for (int kk = 0; kk < 64; kk += 16) {
      wmma::fragment<wmma::matrix_a, 16, 16, 16, __nv_bfloat16, wmma::row_major> fah[2], fal[2];
      wmma::fragment<wmma::matrix_b, 16, 16, 16, __nv_bfloat16, wmma::col_major> fbh[2], fbl[2];
#pragma unroll
      for (int i = 0; i < 2; i++) {
        wmma::load_matrix_sync(fah[i], &aH[(wm * 32 + i * 16) * ALD2 + kk], ALD2);
        wmma::load_matrix_sync(fal[i], &aL[(wm * 32 + i * 16) * ALD2 + kk], ALD2);
        wmma::load_matrix_sync(fbh[i], &bH[(wn * 32 + i * 16) * ALD2 + kk], ALD2);
        wmma::load_matrix_sync(fbl[i], &bL[(wn * 32 + i * 16) * ALD2 + kk], ALD2);
      }
#pragma unroll
      for (int i = 0; i < 2; i++)
#pragma unroll
        for (int j = 0; j < 2; j++) {
          wmma::mma_sync(acc[i][j], fah[i], fbh[j], acc[i][j]);
          wmma::mma_sync(acc[i][j], fah[i], fbl[j], acc[i][j]);
          wmma::mma_sync(acc[i][j], fal[i], fbh[j], acc[i][j]);
        }
    }
    __syncthreads();
  }

  float* Cs = reinterpret_cast<float*>(gsm);  // 128x64 fp32 = 32 KB (fits in A region)
#pragma unroll
  for (int i = 0; i < 2; i++)
#pragma unroll
    for (int j = 0; j < 2; j++)
      wmma::store_matrix_sync(&Cs[(wm * 32 + i * 16) * 64 + wn * 32 + j * 16],
                              acc[i][j], 64, wmma::mem_row_major);
  __syncthreads();
#pragma unroll
  for (int r2 = 0; r2 < 8; r2++) {
    const int idx = tid + r2 * 256;
    const int row = idx >> 4, c4 = (idx & 15) * 4;
    float4 o = *reinterpret_cast<const float4*>(&Cs[row * 64 + c4]);
    if (bias) {
      float4 bb = *reinterpret_cast<const float4*>(&bias[n0 + c4]);
      o.x += bb.x; o.y += bb.y; o.z += bb.z; o.w += bb.w;
    }
    const size_t g = (size_t)(m0 + row) * D_ + n0 + c4;
    if (mode == 0) {
      float4 ub4 = *reinterpret_cast<const float4*>(&ub[n0 + c4]);
      float4 vb4 = *reinterpret_cast<const float4*>(&vb[n0 + c4]);
      float4 cq = make_float4(o.x + ub4.x, o.y + ub4.y, o.z + ub4.z, o.w + ub4.w);
      float4 aq = make_float4(o.x + vb4.x, o.y + vb4.y, o.z + vb4.z, o.w + vb4.w);
      split_store4(cq, g_cqh, g_cql, g);
      split_store4(aq, g_aqh, g_aql, g);
    } else if (mode == 1) {
      split_store4(o, g_khh, g_khl, g);
    } else if (mode == 2) {
      split_store4(o, g_vhh, g_vhl, g);
    } else if (mode == 3) {
      split_store4(o, g_phh, g_phl, g);
    } else {
      *reinterpret_cast<float4*>(&C[g]) = o;
    }
  }
}

__global__ __launch_bounds__(256) void wmma_proj_kernel(
    const float* __restrict__ bq, const float* __restrict__ ub,
    const float* __restrict__ vb) {
  const int z = blockIdx.z;
  const __nv_bfloat16* Ah = g_inh + (size_t)z * BT_ * D_;
  const __nv_bfloat16* Al = g_inl + (size_t)z * BT_ * D_;
  const int ws = (z < 3) ? 0 : 1;
  wmma_gemm_body(Ah, Al, g_wth + (size_t)ws * D_ * D_, g_wtl + (size_t)ws * D_ * D_,
                 (z < 3) ? bq : nullptr, nullptr, blockIdx.y * 128, blockIdx.x * 64,
                 z, ub, vb);
}

__global__ __launch_bounds__(256) void wmma_final_kernel(const float* __restrict__ bf,
                                                         float* __restrict__ out) {
  wmma_gemm_body(g_ctxh, g_ctxl, g_wth + (size_t)2 * D_ * D_, g_wtl + (size_t)2 * D_ * D_,
                 bf, out, blockIdx.y * 128, blockIdx.x * 64, 4, nullptr, nullptr);
}

// =====================================================================
// wmma pscore v3: block = 128(t) x TWO 64-wide j tiles (A loaded once).
// Dynamic smem 52 KB: A splits + B splits; staging overlaps dead B region.
// =====================================================================
#define PSC_A_BYTES (2 * 128 * ALD * 2)      // 20480
#define PSC_SMEM (PSC_A_BYTES + 32768)       // 53248

__global__ __launch_bounds__(256) void wmma_pscore_kernel() {
  extern __shared__ __align__(16) char psm[];
  __nv_bfloat16* aH = reinterpret_cast<__nv_bfloat16*>(psm);
  __nv_bfloat16* aL = aH + 128 * ALD;
  __nv_bfloat16* bH = aL + 128 * ALD;                 // offset 20480
  __nv_bfloat16* bL = bH + 64 * ALD;
  float* Cs = reinterpret_cast<float*>(psm + PSC_A_BYTES);  // overlaps B (dead at staging)

  const int tid = threadIdx.x;
  const int wid = tid >> 5;
  const int wm = wid >> 1, wn = wid & 1;
  const int bz = blockIdx.z, b = bz >> 4, h = bz & 15;
  const int t0 = blockIdx.y * 128;

  // load A splits once (128 t-rows x 32 dims)
#pragma unroll
  for (int r2 = 0; r2 < 2; r2++) {
    const int idx = tid + r2 * 256;
    const int r = idx >> 2, c8 = (idx & 3) * 8;
    const size_t ga = (size_t)(b * T_ + t0 + r) * D_ + h * DH_ + c8;
    *reinterpret_cast<uint4*>(&aH[r * ALD + c8]) = *reinterpret_cast<const uint4*>(&g_aqh[ga]);
    *reinterpret_cast<uint4*>(&aL[r * ALD + c8]) = *reinterpret_cast<const uint4*>(&g_aql[ga]);
  }

#pragma unroll
  for (int jt = 0; jt < 2; jt++) {
    const int j0 = blockIdx.x * 128 + jt * 64;
    __syncthreads();  // prior staging reads done before B region is rewritten
    {
      const int r = tid >> 2, c8 = (tid & 3) * 8;
      const size_t gb = (size_t)(b * T_ + j0 + r) * D_ + h * DH_ + c8;
      *reinterpret_cast<uint4*>(&bH[r * ALD + c8]) = *reinterpret_cast<const uint4*>(&g_phh[gb]);
      *reinterpret_cast<uint4*>(&bL[r * ALD + c8]) = *reinterpret_cast<const uint4*>(&g_phl[gb]);
    }
    __syncthreads();

    wmma::fragment<wmma::accumulator, 16, 16, 16, float> acc[2][2];
#pragma unroll
    for (int i = 0; i < 2; i++)
#pragma unroll
      for (int j = 0; j < 2; j++) wmma::fill_fragment(acc[i][j], 0.f);

#pragma unroll
    for (int kk = 0; kk < 32; kk += 16) {
      wmma::fragment<wmma::matrix_a, 16, 16, 16, __nv_bfloat16, wmma::row_major> fah[2], fal[2];
      wmma::fragment<wmma::matrix_b, 16, 16, 16, __nv_bfloat16, wmma::col_major> fbh[2], fbl[2];
#pragma unroll
      for (int i = 0; i < 2; i++) {
        wmma::load_matrix_sync(fah[i], &aH[(wm * 32 + i * 16) * ALD + kk], ALD);
        wmma::load_matrix_sync(fal[i], &aL[(wm * 32 + i * 16) * ALD + kk], ALD);
        wmma::load_matrix_sync(fbh[i], &bH[(wn * 32 + i * 16) * ALD + kk], ALD);
        wmma::load_matrix_sync(fbl[i], &bL[(wn * 32 + i * 16) * ALD + kk], ALD);
      }
#pragma unroll
      for (int i = 0; i < 2; i++)
#pragma unroll
        for (int j = 0; j < 2; j++) {
          wmma::mma_sync(acc[i][j], fah[i], fbh[j], acc[i][j]);
          wmma::mma_sync(acc[i][j], fah[i], fbl[j], acc[i][j]);
          wmma::mma_sync(acc[i][j], fal[i], fbh[j], acc[i][j]);
        }
    }

    __syncthreads();  // all B frag reads done before staging clobbers B region
#pragma unroll
    for (int i = 0; i < 2; i++)
#pragma unroll
      for (int j = 0; j < 2; j++)
        wmma::store_matrix_sync(&Cs[(wm * 32 + i * 16) * 64 + wn * 32 + j * 16],
                                acc[i][j], 64, wmma::mem_row_major);
    __syncthreads();
#pragma unroll
    for (int it = 0; it < 4; it++) {
      const int e = tid + it * 256;
      const int rs = e >> 3;
      const int c8 = (e & 7) * 8;
      const float* src = &Cs[rs * 64 + c8];
      __half h8[8];
#pragma unroll
      for (int x = 0; x < 8; x++) h8[x] = __float2half(src[x]);
      *reinterpret_cast<uint4*>(
          &g_P[((size_t)bz * T_ + t0 + rs) * T_ + j0 + c8]) =
          *reinterpret_cast<const uint4*>(h8);
    }
  }
}

// =====================================================================
// Flash v5 (validated r15): wmma QK + shift(P fp16) + no-max exp epilogue
// + wmma AV (persistent frags). Unchanged this round.
// =====================================================================
#define VLD 40
#define SLD 68
#define PLD2 72
#define CLD 32
#define OQH 0
#define OQL (OQH + 64 * VLD * 2)
#define OKH (OQL + 64 * VLD * 2)
#define OKL (OKH + 64 * VLD * 2)
#define OVH (OKL + 64 * VLD * 2)
#define OVL (OVH + 64 * VLD * 2)
#define OSS (OVL + 64 * VLD * 2)
#define OPH (OSS + 64 * SLD * 4)
#define OPL (OPH + 64 * PLD2 * 2)
#define OLR (OPL + 64 * PLD2 * 2)
#define FLASH_SMEM (OLR + 64 * 4)

__global__ __launch_bounds__(256) void flash_kernel() {
  extern __shared__ __align__(16) char sm[];
  __nv_bfloat16* QhS = reinterpret_cast<__nv_bfloat16*>(sm + OQH);
  __nv_bfloat16* QlS = reinterpret_cast<__nv_bfloat16*>(sm + OQL);
  __nv_bfloat16* KhS = reinterpret_cast<__nv_bfloat16*>(sm + OKH);
  __nv_bfloat16* KlS = reinterpret_cast<__nv_bfloat16*>(sm + OKL);
  __nv_bfloat16* VhS = reinterpret_cast<__nv_bfloat16*>(sm + OVH);
  __nv_bfloat16* VlS = reinterpret_cast<__nv_bfloat16*>(sm + OVL);
  float* Ss = reinterpret_cast<float*>(sm + OSS);
  __nv_bfloat16* PsH = reinterpret_cast<__nv_bfloat16*>(sm + OPH);
  __nv_bfloat16* PsL = reinterpret_cast<__nv_bfloat16*>(sm + OPL);
  float* rowX = reinterpret_cast<float*>(sm + OLR);

  const int tid = threadIdx.x;
  const int wid = tid >> 5;
  const int wm = wid >> 1, wn = wid & 1;
  const int bz = blockIdx.y, b = bz >> 4, h = bz & 15;
  const int t0 = blockIdx.x * 64;
  const float isd = 0.04419417382415922f;

  const int pr = tid >> 2, pc8 = (tid & 3) * 8;
  {
    const size_t g = (size_t)(b * T_ + t0 + pr) * D_ + h * DH_ + pc8;
    *reinterpret_cast<uint4*>(&QhS[pr * VLD + pc8]) =
        *reinterpret_cast<const uint4*>(&g_cqh[g]);
    *reinterpret_cast<uint4*>(&QlS[pr * VLD + pc8]) =
        *reinterpret_cast<const uint4*>(&g_cql[g]);
  }

  const int tx = tid & 15, ty = tid >> 4;
  float lsum[4] = {0.f, 0.f, 0.f, 0.f};

  wmma::fragment<wmma::accumulator, 16, 16, 16, float> accO;
  wmma::fill_fragment(accO, 0.f);

  for (int c = 0; c < 16; c++) {
    const int s0 = c * 64;
    {
      const size_t g = (size_t)(b * T_ + s0 + pr) * D_ + h * DH_ + pc8;
      *reinterpret_cast<uint4*>(&KhS[pr * VLD + pc8]) =
          *reinterpret_cast<const uint4*>(&g_khh[g]);
      *reinterpret_cast<uint4*>(&KlS[pr * VLD + pc8]) =
          *reinterpret_cast<const uint4*>(&g_khl[g]);
      *reinterpret_cast<uint4*>(&VhS[pr * VLD + pc8]) =
          *reinterpret_cast<const uint4*>(&g_vhh[g]);
      *reinterpret_cast<uint4*>(&VlS[pr * VLD + pc8]) =
          *reinterpret_cast<const uint4*>(&g_vhl[g]);
    }
    __syncthreads();

    {
      wmma::fragment<wmma::accumulator, 16, 16, 16, float> accS[2];
      wmma::fill_fragment(accS[0], 0.f);
      wmma::fill_fragment(accS[1], 0.f);
#pragma unroll
      for (int kk = 0; kk < 32; kk += 16) {
        wmma::fragment<wmma::matrix_a, 16, 16, 16, __nv_bfloat16, wmma::row_major> fah, fal;
        wmma::load_matrix_sync(fah, &QhS[(wm * 16) * VLD + kk], VLD);
        wmma::load_matrix_sync(fal, &QlS[(wm * 16) * VLD + kk], VLD);
#pragma unroll
        for (int j = 0; j < 2; j++) {
          wmma::fragment<wmma::matrix_b, 16, 16, 16, __nv_bfloat16, wmma::col_major> fbh, fbl;
          wmma::load_matrix_sync(fbh, &KhS[(wn * 32 + j * 16) * VLD + kk], VLD);
          wmma::load_matrix_sync(fbl, &KlS[(wn * 32 + j * 16) * VLD + kk], VLD);
          wmma::mma_sync(accS[j], fah, fbh, accS[j]);
          wmma::mma_sync(accS[j], fah, fbl, accS[j]);
          wmma::mma_sync(accS[j], fal, fbh, accS[j]);
        }
      }
      wmma::store_matrix_sync(&Ss[(wm * 16) * SLD + wn * 32], accS[0], SLD,
                              wmma::mem_row_major);
      wmma::store_matrix_sync(&Ss[(wm * 16) * SLD + wn * 32 + 16], accS[1], SLD,
                              wmma::mem_row_major);
    }
    __syncthreads();

#pragma unroll
    for (int i = 0; i < 4; i++) {
      const int trow = ty * 4 + i;
      const int t = t0 + trow;
      const size_t rowb = ((size_t)bz * T_ + t) * T_;
      float v[4];
#pragma unroll
      for (int j = 0; j < 4; j++) {
        const int s = s0 + tx * 4 + j;
        float pv;
        if (s <= t)          pv = __half2float(g_P[rowb + (s - t + (T_ - 1))]);
        else if (s == t + 1) pv = 0.f;
        else                 pv = __half2float(g_P[rowb + T_ + (s - t - 2)]);
        v[j] = __expf((Ss[trow * SLD + tx * 4 + j] + pv) * isd);
      }
      lsum[i] += (v[0] + v[1]) + (v[2] + v[3]);
      __nv_bfloat162 h01, h23, l01, l23;
      split_bf16(v[0], h01.x, l01.x); split_bf16(v[1], h01.y, l01.y);
      split_bf16(v[2], h23.x, l23.x); split_bf16(v[3], h23.y, l23.y);
      *reinterpret_cast<__nv_bfloat162*>(&PsH[trow * PLD2 + tx * 4]) = h01;
      *reinterpret_cast<__nv_bfloat162*>(&PsH[trow * PLD2 + tx * 4 + 2]) = h23;
      *reinterpret_cast<__nv_bfloat162*>(&PsL[trow * PLD2 + tx * 4]) = l01;
      *reinterpret_cast<__nv_bfloat162*>(&PsL[trow * PLD2 + tx * 4 + 2]) = l23;
    }
    __syncthreads();

#pragma unroll
    for (int kk = 0; kk < 64; kk += 16) {
      wmma::fragment<wmma::matrix_a, 16, 16, 16, __nv_bfloat16, wmma::row_major> pah, pal;
      wmma::fragment<wmma::matrix_b, 16, 16, 16, __nv_bfloat16, wmma::row_major> fvh, fvl;
      wmma::load_matrix_sync(pah, &PsH[(wm * 16) * PLD2 + kk], PLD2);
      wmma::load_matrix_sync(pal, &PsL[(wm * 16) * PLD2 + kk], PLD2);
      wmma::load_matrix_sync(fvh, &VhS[kk * VLD + wn * 16], VLD);
      wmma::load_matrix_sync(fvl, &VlS[kk * VLD + wn * 16], VLD);
      wmma::mma_sync(accO, pah, fvh, accO);
      wmma::mma_sync(accO, pah, fvl, accO);
      wmma::mma_sync(accO, pal, fvh, accO);
    }
    __syncthreads();
  }

#pragma unroll
  for (int i = 0; i < 4; i++) {
    float l = lsum[i];
    l += __shfl_xor_sync(0xffffffffu, l, 1);
    l += __shfl_xor_sync(0xffffffffu, l, 2);
    l += __shfl_xor_sync(0xffffffffu, l, 4);
    l += __shfl_xor_sync(0xffffffffu, l, 8);
    if (tx == 0) rowX[ty * 4 + i] = 1.0f / l;
  }
  float* Cs = Ss;
  wmma::store_matrix_sync(&Cs[(wm * 16) * CLD + wn * 16], accO, CLD,
                          wmma::mem_row_major);
  __syncthreads();
  {
    const int row = tid >> 2, c8 = (tid & 3) * 8;
    const float inv = rowX[row];
    float4 a = *reinterpret_cast<const float4*>(&Cs[row * CLD + c8]);
    float4 bb = *reinterpret_cast<const float4*>(&Cs[row * CLD + c8 + 4]);
    a.x *= inv; a.y *= inv; a.z *= inv; a.w *= inv;
    bb.x *= inv; bb.y *= inv; bb.z *= inv; bb.w *= inv;
    const size_t base = (size_t)(b * T_ + t0 + row) * D_ + h * DH_ + c8;
    split_store4(a, g_ctxh, g_ctxl, base);
    split_store4(bb, g_ctxh, g_ctxl, base + 4);
  }
}

// =====================================================================
extern "C" void kernel_launch(void* const* d_in, const int* in_sizes, int n_in,
                              void* d_out, int out_size) {
  const float* q   = (const float*)d_in[0];
  const float* k   = (const float*)d_in[1];
  const float* v   = (const float*)d_in[2];
  const float* pos = (const float*)d_in[3];
  const float* Wq  = (const float*)d_in[4];
  const float* bq  = (const float*)d_in[5];
  const float* Wp  = (const float*)d_in[6];
  const float* Wf  = (const float*)d_in[7];
  const float* bf  = (const float*)d_in[8];
  const float* ub  = (const float*)d_in[9];
  const float* vb  = (const float*)d_in[10];
  float* out = (float*)d_out;

  static bool attr_done = false;
  if (!attr_done) {
    cudaFuncSetAttribute(flash_kernel,
                         cudaFuncAttributeMaxDynamicSharedMemorySize, FLASH_SMEM);
    cudaFuncSetAttribute(wmma_proj_kernel,
                         cudaFuncAttributeMaxDynamicSharedMemorySize, GEMM_SMEM);
    cudaFuncSetAttribute(wmma_final_kernel,
                         cudaFuncAttributeMaxDynamicSharedMemorySize, GEMM_SMEM);
    cudaFuncSetAttribute(wmma_pscore_kernel,
                         cudaFuncAttributeMaxDynamicSharedMemorySize, PSC_SMEM);
    attr_done = true;
  }

  convert_inputs_kernel<<<dim3(BT_ * D_ / 1024, 4), 256>>>(q, k, v, pos);
  convert_w_kernel<<<dim3(16, 16, 3), 256>>>(Wq, Wp, Wf);

  wmma_proj_kernel<<<dim3(8, 32, 4), 256, GEMM_SMEM>>>(bq, ub, vb);

  wmma_pscore_kernel<<<dim3(8, 8, 64), 256, PSC_SMEM>>>();

  flash_kernel<<<dim3(16, 64), 256, FLASH_SMEM>>>();

  wmma_final_kernel<<<dim3(8, 32), 256, GEMM_SMEM>>>(bf, out);
}